// round 1
// baseline (speedup 1.0000x reference)
#include <cuda_runtime.h>
#include <math.h>

#define Bk 8
#define Ck 64
#define Hk 128
#define Wk 128
#define NPIX (Hk*Wk)                 // 16384
#define PLANE (Ck*NPIX)              // 1,048,576 per batch
#define TENSOR (Bk*PLANE)            // 8,388,608 elements
#define WSET (9*64*64)               // 36864 per weight set

// Scratch (device globals; no allocation)
__device__ float g_tmp_sr[TENSOR];
__device__ float g_tmp_edge[TENSOR];
__device__ float g_kern[Bk * 9 * NPIX];
__device__ float g_wT[4 * WSET];     // [set][tap][cin][cout]

// ---------------------------------------------------------------------------
// Weight transpose: w[o][c][ky][kx] -> wT[set][p][c][o]
// ---------------------------------------------------------------------------
__global__ void transpose_weights(const float* __restrict__ w0,
                                  const float* __restrict__ w1,
                                  const float* __restrict__ w2,
                                  const float* __restrict__ w3) {
    int idx = blockIdx.x * blockDim.x + threadIdx.x;
    if (idx >= WSET) return;
    int o = idx & 63;
    int c = (idx >> 6) & 63;
    int p = idx >> 12;                      // 0..8, p = ky*3+kx
    int src = (o * 64 + c) * 9 + p;
    g_wT[0 * WSET + idx] = w0[src];
    g_wT[1 * WSET + idx] = w1[src];
    g_wT[2 * WSET + idx] = w2[src];
    g_wT[3 * WSET + idx] = w3[src];
}

// ---------------------------------------------------------------------------
// Adaptive-kernel field: kern[b][p][h][w] = exp(-0.5 * sum_c (g_nb - g_ctr)^2)
// guide zero-padded outside (matches jnp.pad).
// grid: (Hk, Bk), block: 128 threads (one per w)
// ---------------------------------------------------------------------------
__global__ void kern_field_kernel(const float* __restrict__ g,
                                  float* __restrict__ kout) {
    int h = blockIdx.x;
    int b = blockIdx.y;
    int w = threadIdx.x;

    __shared__ float srow[3][130];   // cols -1..128 (halo zeros)

    float d2[9];
#pragma unroll
    for (int p = 0; p < 9; p++) d2[p] = 0.f;

    const float* gb = g + b * PLANE;

    for (int c = 0; c < Ck; c++) {
        const float* gc = gb + c * NPIX;
#pragma unroll
        for (int r = 0; r < 3; r++) {
            int hh = h + r - 1;
            srow[r][w + 1] = (hh >= 0 && hh < Hk) ? gc[hh * Wk + w] : 0.f;
        }
        if (w == 0) {
#pragma unroll
            for (int r = 0; r < 3; r++) { srow[r][0] = 0.f; srow[r][129] = 0.f; }
        }
        __syncthreads();
        float ctr = srow[1][w + 1];
#pragma unroll
        for (int p = 0; p < 9; p++) {
            int dy = p / 3, dx = p % 3;
            float diff = srow[dy][w + dx] - ctr;
            d2[p] += diff * diff;
        }
        __syncthreads();
    }

#pragma unroll
    for (int p = 0; p < 9; p++)
        kout[((b * 9 + p) * Hk + h) * Wk + w] = expf(-0.5f * d2[p]);
}

// ---------------------------------------------------------------------------
// Unified 3x3 conv (PAC when kern != null, plain otherwise).
// Per block: 64 cout x 64 pixels (one row segment), 9 tap-GEMMs K=64.
// Epilogue: +bias, optional ReLU, optional residual add.
// grid: (2, Hk, Bk), block: 256 threads
// ---------------------------------------------------------------------------
__global__ void __launch_bounds__(256, 4)
conv3x3_kernel(const float* __restrict__ x,
               const float* __restrict__ kern,     // may be null
               const float* __restrict__ wT,       // [9][64 cin][64 cout]
               const float* __restrict__ bias,
               const float* __restrict__ resid,    // may be null
               float* __restrict__ out,
               int do_relu) {
    __shared__ float w_s[64 * 64];   // [cin][cout]
    __shared__ float x_s[64 * 64];   // [cin][pix] (kern folded)
    __shared__ float k_s[9 * 64];    // [tap][pix]

    const int seg = blockIdx.x;          // 0/1
    const int h   = blockIdx.y;
    const int b   = blockIdx.z;
    const int w0  = seg * 64;
    const int tid = threadIdx.x;
    const int tx  = tid & 15;            // pixel group
    const int ty  = tid >> 4;            // cout group

    // stage kern row (or ones)
    for (int idx = tid; idx < 9 * 64; idx += 256) {
        int p = idx >> 6, pix = idx & 63;
        k_s[idx] = kern ? kern[((b * 9 + p) * Hk + h) * Wk + w0 + pix] : 1.0f;
    }

    float acc[4][4];
#pragma unroll
    for (int i = 0; i < 4; i++)
#pragma unroll
        for (int j = 0; j < 4; j++) acc[i][j] = 0.f;

    const float* xb = x + b * PLANE;

    for (int p = 0; p < 9; p++) {
        const int dy = p / 3 - 1, dx = p % 3 - 1;
        const int row = h + dy;
        const bool rowok = (row >= 0) && (row < Hk);

        __syncthreads();   // also covers k_s on first iteration

        // stage weights for this tap (coalesced from L2)
        for (int idx = tid; idx < 4096; idx += 256)
            w_s[idx] = wT[p * 4096 + idx];

        // stage x neighbors with kern scaling + zero padding
        for (int idx = tid; idx < 4096; idx += 256) {
            int c = idx >> 6, pix = idx & 63;
            int col = w0 + dx + pix;
            float v = 0.f;
            if (rowok && col >= 0 && col < Wk)
                v = xb[c * NPIX + row * Wk + col];
            x_s[idx] = v * k_s[p * 64 + pix];
        }
        __syncthreads();

#pragma unroll 16
        for (int k = 0; k < 64; k++) {
            float4 wv = *(const float4*)&w_s[k * 64 + ty * 4];
            float4 xv = *(const float4*)&x_s[k * 64 + tx * 4];
            acc[0][0] += wv.x * xv.x; acc[0][1] += wv.x * xv.y;
            acc[0][2] += wv.x * xv.z; acc[0][3] += wv.x * xv.w;
            acc[1][0] += wv.y * xv.x; acc[1][1] += wv.y * xv.y;
            acc[1][2] += wv.y * xv.z; acc[1][3] += wv.y * xv.w;
            acc[2][0] += wv.z * xv.x; acc[2][1] += wv.z * xv.y;
            acc[2][2] += wv.z * xv.z; acc[2][3] += wv.z * xv.w;
            acc[3][0] += wv.w * xv.x; acc[3][1] += wv.w * xv.y;
            acc[3][2] += wv.w * xv.z; acc[3][3] += wv.w * xv.w;
        }
    }

    // epilogue: bias, relu / residual, float4 store
#pragma unroll
    for (int i = 0; i < 4; i++) {
        int o = ty * 4 + i;
        float bv = bias[o];
        float4 r;
        r.x = acc[i][0] + bv; r.y = acc[i][1] + bv;
        r.z = acc[i][2] + bv; r.w = acc[i][3] + bv;
        if (do_relu) {
            r.x = fmaxf(r.x, 0.f); r.y = fmaxf(r.y, 0.f);
            r.z = fmaxf(r.z, 0.f); r.w = fmaxf(r.w, 0.f);
        }
        int off = ((b * Ck + o) * Hk + h) * Wk + w0 + tx * 4;
        if (resid) {
            float4 rv = *(const float4*)&resid[off];
            r.x += rv.x; r.y += rv.y; r.z += rv.z; r.w += rv.w;
        }
        *(float4*)&out[off] = r;
    }
}

// ---------------------------------------------------------------------------
extern "C" void kernel_launch(void* const* d_in, const int* in_sizes, int n_in,
                              void* d_out, int out_size) {
    const float* x      = (const float*)d_in[0];
    const float* edge   = (const float*)d_in[1];
    const float* w_pac1 = (const float*)d_in[2];
    const float* b_pac1 = (const float*)d_in[3];
    const float* w_pac2 = (const float*)d_in[4];
    const float* b_pac2 = (const float*)d_in[5];
    const float* w_e1   = (const float*)d_in[6];
    const float* b_e1   = (const float*)d_in[7];
    const float* w_e2   = (const float*)d_in[8];
    const float* b_e2   = (const float*)d_in[9];

    float* out_sr   = (float*)d_out;
    float* out_edge = out_sr + TENSOR;

    float *p_tmp_sr, *p_tmp_edge, *p_kern, *p_wT;
    cudaGetSymbolAddress((void**)&p_tmp_sr, g_tmp_sr);
    cudaGetSymbolAddress((void**)&p_tmp_edge, g_tmp_edge);
    cudaGetSymbolAddress((void**)&p_kern, g_kern);
    cudaGetSymbolAddress((void**)&p_wT, g_wT);

    // weights -> [tap][cin][cout] per set: 0=pac1, 1=pac2, 2=e1, 3=e2
    transpose_weights<<<(WSET + 255) / 256, 256>>>(w_pac1, w_pac2, w_e1, w_e2);

    dim3 kgrid(Hk, Bk);
    dim3 cgrid(2, Hk, Bk);

    // stage 1: kern(edge); res_sr = relu(pac(x)); res_edge = relu(conv(edge))
    kern_field_kernel<<<kgrid, 128>>>(edge, p_kern);
    conv3x3_kernel<<<cgrid, 256>>>(x,    p_kern,  p_wT + 0 * WSET, b_pac1,
                                   nullptr, p_tmp_sr,   1);
    conv3x3_kernel<<<cgrid, 256>>>(edge, nullptr, p_wT + 2 * WSET, b_e1,
                                   nullptr, p_tmp_edge, 1);

    // stage 2: kern(res_edge); out_sr = x + pac(res_sr); out_edge = edge + conv(res_edge)
    kern_field_kernel<<<kgrid, 128>>>(p_tmp_edge, p_kern);
    conv3x3_kernel<<<cgrid, 256>>>(p_tmp_sr,   p_kern,  p_wT + 1 * WSET, b_pac2,
                                   x,    out_sr,   0);
    conv3x3_kernel<<<cgrid, 256>>>(p_tmp_edge, nullptr, p_wT + 3 * WSET, b_e2,
                                   edge, out_edge, 0);
}

// round 2
// speedup vs baseline: 1.1099x; 1.1099x over previous
#include <cuda_runtime.h>
#include <math.h>

#define Bk 8
#define Ck 64
#define Hk 128
#define Wk 128
#define NPIX (Hk*Wk)                 // 16384
#define PLANE (Ck*NPIX)              // 1,048,576 per batch
#define TENSOR (Bk*PLANE)            // 8,388,608 elements
#define WSET (9*64*64)               // 36864 per weight set

// Scratch (device globals; no allocation)
__device__ float g_tmp_sr[TENSOR];
__device__ float g_tmp_edge[TENSOR];
__device__ float g_kern[Bk * 9 * NPIX];
__device__ float g_wT[4 * WSET];     // [set][tap][cin][cout]

// ---------------------------------------------------------------------------
// Weight transpose: w[o][c][ky][kx] -> wT[set][p][c][o]
// ---------------------------------------------------------------------------
__global__ void transpose_weights(const float* __restrict__ w0,
                                  const float* __restrict__ w1,
                                  const float* __restrict__ w2,
                                  const float* __restrict__ w3) {
    int idx = blockIdx.x * blockDim.x + threadIdx.x;
    if (idx >= WSET) return;
    int o = idx & 63;
    int c = (idx >> 6) & 63;
    int p = idx >> 12;                      // 0..8, p = ky*3+kx
    int src = (o * 64 + c) * 9 + p;
    g_wT[0 * WSET + idx] = w0[src];
    g_wT[1 * WSET + idx] = w1[src];
    g_wT[2 * WSET + idx] = w2[src];
    g_wT[3 * WSET + idx] = w3[src];
}

// ---------------------------------------------------------------------------
// Adaptive-kernel field: kern[b][p][h][w] = exp(-0.5 * sum_c (g_nb - g_ctr)^2)
// grid: (Hk, Bk), block: 128 threads (one per w)
// ---------------------------------------------------------------------------
__global__ void kern_field_kernel(const float* __restrict__ g,
                                  float* __restrict__ kout) {
    int h = blockIdx.x;
    int b = blockIdx.y;
    int w = threadIdx.x;

    __shared__ float srow[3][130];   // cols -1..128 (halo zeros)

    float d2[9];
#pragma unroll
    for (int p = 0; p < 9; p++) d2[p] = 0.f;

    const float* gb = g + b * PLANE;

    for (int c = 0; c < Ck; c++) {
        const float* gc = gb + c * NPIX;
#pragma unroll
        for (int r = 0; r < 3; r++) {
            int hh = h + r - 1;
            srow[r][w + 1] = (hh >= 0 && hh < Hk) ? gc[hh * Wk + w] : 0.f;
        }
        if (w == 0) {
#pragma unroll
            for (int r = 0; r < 3; r++) { srow[r][0] = 0.f; srow[r][129] = 0.f; }
        }
        __syncthreads();
        float ctr = srow[1][w + 1];
#pragma unroll
        for (int p = 0; p < 9; p++) {
            int dy = p / 3, dx = p % 3;
            float diff = srow[dy][w + dx] - ctr;
            d2[p] += diff * diff;
        }
        __syncthreads();
    }

#pragma unroll
    for (int p = 0; p < 9; p++)
        kout[((b * 9 + p) * Hk + h) * Wk + w] = expf(-0.5f * d2[p]);
}

// ---------------------------------------------------------------------------
// Unified 3x3 conv (PAC when kern != null, plain otherwise), 8x8 reg tiles.
// Block tile: 64 cout x 128 pixels (one full image row). 128 threads.
// Thread (ty,tx): couts {ty*4+i, 32+ty*4+i}, pixels {tx*4+j, 64+tx*4+j}.
// grid: (Hk, Bk), block: 128 threads, dynamic smem 53760 B
// ---------------------------------------------------------------------------
__global__ void __launch_bounds__(128, 4)
conv3x3_kernel(const float* __restrict__ x,
               const float* __restrict__ kern,     // may be null
               const float* __restrict__ wT,       // [9][64 cin][64 cout]
               const float* __restrict__ bias,
               const float* __restrict__ resid,    // may be null
               float* __restrict__ out,
               int do_relu) {
    extern __shared__ float smem[];
    float* w_s = smem;                 // [64 k][64 o]   = 4096
    float* x_s = smem + 4096;          // [64 k][128 px] = 8192
    float* k_s = smem + 12288;         // [9 p][128 px]  = 1152

    const int h   = blockIdx.x;
    const int b   = blockIdx.y;
    const int tid = threadIdx.x;
    const int tx  = tid & 15;            // pixel group (0..15)
    const int ty  = tid >> 4;            // cout group  (0..7)

    // stage kern rows (or ones): i = tid + n*128 -> p = n, pix = tid
    for (int i = tid; i < 9 * 128; i += 128) {
        int p = i >> 7, pix = i & 127;
        k_s[i] = kern ? kern[((b * 9 + p) * Hk + h) * Wk + pix] : 1.0f;
    }

    float acc[8][8];
#pragma unroll
    for (int i = 0; i < 8; i++)
#pragma unroll
        for (int j = 0; j < 8; j++) acc[i][j] = 0.f;

    const float* xb = x + b * PLANE;
    const float4* w4s = (const float4*)w_s;
    const float4* x4s = (const float4*)x_s;

    for (int p = 0; p < 9; p++) {
        const int dy = p / 3 - 1, dx = p % 3 - 1;
        const int row = h + dy;

        __syncthreads();   // previous tap's reads done; covers k_s for p=0

        // stage weights for this tap: 1024 float4 / 128 threads = 8 each
        {
            const float4* wsrc = (const float4*)(wT + p * 4096);
            float4* wd = (float4*)w_s;
#pragma unroll
            for (int n = 0; n < 8; n++)
                wd[tid + n * 128] = wsrc[tid + n * 128];
        }

        // stage x: one pixel-column per thread across all 64 channels
        {
            const int pix = tid;
            const int col = pix + dx;
            const bool ok = (row >= 0) && (row < Hk) && (col >= 0) && (col < Wk);
            const float kv = k_s[p * 128 + pix];
            const float* src = xb + row * Wk + col;
            if (ok) {
#pragma unroll 8
                for (int c = 0; c < 64; c++)
                    x_s[c * 128 + pix] = src[c * NPIX] * kv;
            } else {
#pragma unroll 8
                for (int c = 0; c < 64; c++)
                    x_s[c * 128 + pix] = 0.f;
            }
        }
        __syncthreads();

#pragma unroll 4
        for (int k = 0; k < 64; k++) {
            float wr[8], xr[8];
            float4 t;
            t = w4s[k * 16 + ty];       wr[0]=t.x; wr[1]=t.y; wr[2]=t.z; wr[3]=t.w;
            t = w4s[k * 16 + 8 + ty];   wr[4]=t.x; wr[5]=t.y; wr[6]=t.z; wr[7]=t.w;
            t = x4s[k * 32 + tx];       xr[0]=t.x; xr[1]=t.y; xr[2]=t.z; xr[3]=t.w;
            t = x4s[k * 32 + 16 + tx];  xr[4]=t.x; xr[5]=t.y; xr[6]=t.z; xr[7]=t.w;
#pragma unroll
            for (int i = 0; i < 8; i++)
#pragma unroll
                for (int j = 0; j < 8; j++)
                    acc[i][j] += wr[i] * xr[j];
        }
    }

    // epilogue: bias, relu / residual, float4 stores
#pragma unroll
    for (int i = 0; i < 8; i++) {
        int o = (i < 4) ? (ty * 4 + i) : (32 + ty * 4 + (i - 4));
        float bv = bias[o];
        int base = ((b * Ck + o) * Hk + h) * Wk;
#pragma unroll
        for (int half = 0; half < 2; half++) {
            int px = tx * 4 + half * 64;
            float4 r;
            r.x = acc[i][half*4+0] + bv; r.y = acc[i][half*4+1] + bv;
            r.z = acc[i][half*4+2] + bv; r.w = acc[i][half*4+3] + bv;
            if (do_relu) {
                r.x = fmaxf(r.x, 0.f); r.y = fmaxf(r.y, 0.f);
                r.z = fmaxf(r.z, 0.f); r.w = fmaxf(r.w, 0.f);
            }
            if (resid) {
                float4 rv = *(const float4*)&resid[base + px];
                r.x += rv.x; r.y += rv.y; r.z += rv.z; r.w += rv.w;
            }
            *(float4*)&out[base + px] = r;
        }
    }
}

#define CONV_SMEM (13440 * 4)

// ---------------------------------------------------------------------------
extern "C" void kernel_launch(void* const* d_in, const int* in_sizes, int n_in,
                              void* d_out, int out_size) {
    const float* x      = (const float*)d_in[0];
    const float* edge   = (const float*)d_in[1];
    const float* w_pac1 = (const float*)d_in[2];
    const float* b_pac1 = (const float*)d_in[3];
    const float* w_pac2 = (const float*)d_in[4];
    const float* b_pac2 = (const float*)d_in[5];
    const float* w_e1   = (const float*)d_in[6];
    const float* b_e1   = (const float*)d_in[7];
    const float* w_e2   = (const float*)d_in[8];
    const float* b_e2   = (const float*)d_in[9];

    float* out_sr   = (float*)d_out;
    float* out_edge = out_sr + TENSOR;

    float *p_tmp_sr, *p_tmp_edge, *p_kern, *p_wT;
    cudaGetSymbolAddress((void**)&p_tmp_sr, g_tmp_sr);
    cudaGetSymbolAddress((void**)&p_tmp_edge, g_tmp_edge);
    cudaGetSymbolAddress((void**)&p_kern, g_kern);
    cudaGetSymbolAddress((void**)&p_wT, g_wT);

    cudaFuncSetAttribute(conv3x3_kernel,
                         cudaFuncAttributeMaxDynamicSharedMemorySize, CONV_SMEM);

    // weights -> [tap][cin][cout] per set: 0=pac1, 1=pac2, 2=e1, 3=e2
    transpose_weights<<<(WSET + 255) / 256, 256>>>(w_pac1, w_pac2, w_e1, w_e2);

    dim3 kgrid(Hk, Bk);
    dim3 cgrid(Hk, Bk);

    // stage 1: kern(edge); res_sr = relu(pac(x)); res_edge = relu(conv(edge))
    kern_field_kernel<<<kgrid, 128>>>(edge, p_kern);
    conv3x3_kernel<<<cgrid, 128, CONV_SMEM>>>(x,    p_kern,  p_wT + 0 * WSET, b_pac1,
                                              nullptr, p_tmp_sr,   1);
    conv3x3_kernel<<<cgrid, 128, CONV_SMEM>>>(edge, nullptr, p_wT + 2 * WSET, b_e1,
                                              nullptr, p_tmp_edge, 1);

    // stage 2: kern(res_edge); out_sr = x + pac(res_sr); out_edge = edge + conv(res_edge)
    kern_field_kernel<<<kgrid, 128>>>(p_tmp_edge, p_kern);
    conv3x3_kernel<<<cgrid, 128, CONV_SMEM>>>(p_tmp_sr,   p_kern,  p_wT + 1 * WSET, b_pac2,
                                              x,    out_sr,   0);
    conv3x3_kernel<<<cgrid, 128, CONV_SMEM>>>(p_tmp_edge, nullptr, p_wT + 3 * WSET, b_e2,
                                              edge, out_edge, 0);
}

// round 4
// speedup vs baseline: 1.6337x; 1.4720x over previous
#include <cuda_runtime.h>
#include <cuda_bf16.h>
#include <cstdint>
#include <math.h>

#define Bk 8
#define Ck 64
#define Hk 128
#define Wk 128
#define NPIX (Hk*Wk)                 // 16384
#define PLANE (Ck*NPIX)              // 1,048,576 per batch
#define TENSOR (Bk*PLANE)            // 8,388,608 elements

// ---------------------------------------------------------------------------
// Scratch (device globals; no allocation)
// ---------------------------------------------------------------------------
__device__ float g_tmp_sr[TENSOR];
__device__ float g_tmp_edge[TENSOR];
__device__ float g_kern[Bk * 9 * NPIX];
// packed bf16 weight fragments: [set 4][tap 9][term 2][kc 4][nc 8][lane 32][reg 2] u32
__device__ uint32_t g_wpk[4 * 9 * 4096];

// ---------------------------------------------------------------------------
// mma.sync m16n8k16 row.col f32.bf16.bf16.f32 (base-target PTX, sm_80+)
// ---------------------------------------------------------------------------
#define MMA16816(c, A0, A1, A2, A3, B0, B1)                                  \
    asm volatile(                                                            \
        "mma.sync.aligned.m16n8k16.row.col.f32.bf16.bf16.f32 "               \
        "{%0,%1,%2,%3},{%4,%5,%6,%7},{%8,%9},{%0,%1,%2,%3};"                 \
        : "+f"((c)[0]), "+f"((c)[1]), "+f"((c)[2]), "+f"((c)[3])             \
        : "r"(A0), "r"(A1), "r"(A2), "r"(A3), "r"(B0), "r"(B1))

// ---------------------------------------------------------------------------
// Weight prep: w[o][c][p] -> fragment-packed bf16 hi/lo u32 words.
// B fragment (m16n8k16, col-major B): reg r of lane l holds
//   { B[kc*16 + (l&3)*2 + r*8][nc*8 + (l>>2)], B[same k +1][same n] }
// with B[k][n] = w[o=n][c=k]. Low half-word = lower-k element.
// ---------------------------------------------------------------------------
__global__ void prep_weights(const float* __restrict__ w0,
                             const float* __restrict__ w1,
                             const float* __restrict__ w2,
                             const float* __restrict__ w3) {
    int idx = blockIdx.x * blockDim.x + threadIdx.x;
    if (idx >= 4 * 9 * 4096) return;
    int s    = idx / 36864;
    int rem  = idx % 36864;
    int p    = rem / 4096;
    int rem2 = rem % 4096;
    int t  = (rem2 >> 11) & 1;
    int kc = (rem2 >> 9) & 3;
    int nc = (rem2 >> 6) & 7;
    int l  = (rem2 >> 1) & 31;
    int r  = rem2 & 1;

    int o = nc * 8 + (l >> 2);
    int k = kc * 16 + (l & 3) * 2 + r * 8;

    const float* w = (s == 0) ? w0 : (s == 1) ? w1 : (s == 2) ? w2 : w3;
    float v0 = w[(o * 64 + k) * 9 + p];
    float v1 = w[(o * 64 + k + 1) * 9 + p];

    __nv_bfloat16 h0 = __float2bfloat16_rn(v0);
    __nv_bfloat16 h1 = __float2bfloat16_rn(v1);
    __nv_bfloat16 e0, e1;
    if (t == 0) { e0 = h0; e1 = h1; }
    else {
        e0 = __float2bfloat16_rn(v0 - __bfloat162float(h0));
        e1 = __float2bfloat16_rn(v1 - __bfloat162float(h1));
    }
    uint32_t pk = ((uint32_t)*(uint16_t*)&e1 << 16) | (uint32_t)*(uint16_t*)&e0;
    g_wpk[idx] = pk;
}

// ---------------------------------------------------------------------------
// Adaptive-kernel field, 16-channel chunks (8 barriers total per block)
// grid: (Hk, Bk), block: 128
// ---------------------------------------------------------------------------
__global__ void kern_field_kernel(const float* __restrict__ g,
                                  float* __restrict__ kout) {
    int h = blockIdx.x;
    int bb = blockIdx.y;
    int w = threadIdx.x;

    __shared__ float s[16 * 3 * 132];

    float d2[9];
#pragma unroll
    for (int p = 0; p < 9; p++) d2[p] = 0.f;

    const float* gb = g + bb * PLANE;

    for (int c0 = 0; c0 < 64; c0 += 16) {
        __syncthreads();
        for (int i = threadIdx.x; i < 16 * 3 * 130; i += 128) {
            int cc = i % 130;
            int rr = (i / 130) % 3;
            int cl = i / 390;
            int row = h + rr - 1, col = cc - 1;
            float v = 0.f;
            if (row >= 0 && row < Hk && col >= 0 && col < Wk)
                v = gb[(c0 + cl) * NPIX + row * Wk + col];
            s[(cl * 3 + rr) * 132 + cc] = v;
        }
        __syncthreads();
#pragma unroll 4
        for (int cl = 0; cl < 16; cl++) {
            float ctr = s[(cl * 3 + 1) * 132 + w + 1];
#pragma unroll
            for (int p = 0; p < 9; p++) {
                float diff = s[(cl * 3 + p / 3) * 132 + w + (p % 3)] - ctr;
                d2[p] += diff * diff;
            }
        }
    }

#pragma unroll
    for (int p = 0; p < 9; p++)
        kout[((bb * 9 + p) * Hk + h) * Wk + w] = expf(-0.5f * d2[p]);
}

// ---------------------------------------------------------------------------
// HMMA conv: one block = one image row (M=128 pix, N=64 cout), 256 thr/8 warps.
// bf16 3-term split, 9 taps, fp32 accumulation in registers.
// blockIdx.z selects between two independent convs (pac / edge paths).
// ---------------------------------------------------------------------------
#define SM_KS   0          // 9*128 floats   = 4608 B
#define SM_AH   4608       // 128 * 144 B    = 18432
#define SM_AL   23040      // 128 * 144 B    = 18432
#define SM_B    41472      // 16384 B
#define CONV_SMEM 57856

__global__ void __launch_bounds__(256, 2)
conv3x3_hmma_kernel(const float* __restrict__ x0,
                    const float* __restrict__ kern0,   // null => plain conv
                    const uint32_t* __restrict__ wt0,  // [9][4096] packed
                    const float* __restrict__ bias0,
                    const float* __restrict__ resid0,
                    float* __restrict__ out0,
                    const float* __restrict__ x1,
                    const uint32_t* __restrict__ wt1,
                    const float* __restrict__ bias1,
                    const float* __restrict__ resid1,
                    float* __restrict__ out1,
                    int do_relu) {
    extern __shared__ char smem[];
    float* k_s = (float*)(smem + SM_KS);

    const int h  = blockIdx.x;
    const int bb = blockIdx.y;
    const int z  = blockIdx.z;

    const float*    x     = z ? x1 : x0;
    const float*    kern  = z ? nullptr : kern0;
    const uint32_t* wt    = z ? wt1 : wt0;
    const float*    bias  = z ? bias1 : bias0;
    const float*    resid = z ? resid1 : resid0;
    float*          out   = z ? out1 : out0;

    const int tid  = threadIdx.x;
    const int warp = tid >> 5;
    const int lane = tid & 31;
    const int gq   = lane >> 2;          // group 0..7
    const int tq   = lane & 3;           // 0..3

    // stage kern rows (or ones)
    for (int i = tid; i < 9 * 128; i += 256) {
        int p = i >> 7, pix = i & 127;
        k_s[i] = kern ? kern[((bb * 9 + p) * Hk + h) * Wk + pix] : 1.0f;
    }

    float acc[8][4];
#pragma unroll
    for (int n = 0; n < 8; n++)
#pragma unroll
        for (int i = 0; i < 4; i++) acc[n][i] = 0.f;

    const float* xb = x + bb * PLANE;

    for (int p = 0; p < 9; p++) {
        __syncthreads();   // prev tap's LDS reads done; k_s ready on p=0

        // stage B: 16 KB fragment-packed copy (1024 uint4)
        {
            const uint4* src = (const uint4*)(wt + p * 4096);
            uint4* dst = (uint4*)(smem + SM_B);
#pragma unroll
            for (int n = 0; n < 4; n++)
                dst[tid + n * 256] = src[tid + n * 256];
        }

        // stage A: [pix][k] bf16 hi/lo, row pitch 144B; kern folded
        {
            const int dy = p / 3 - 1, dx = p % 3 - 1;
            const int pix = tid >> 1;
            const int khalf = (tid & 1) << 5;      // 0 or 32
            const int row = h + dy, col = pix + dx;
            const bool ok = (row >= 0) && (row < Hk) && (col >= 0) && (col < Wk);
            const float kv = k_s[p * 128 + pix];
            const float* src = xb + (size_t)khalf * NPIX + row * Wk + col;
            char* ah = smem + SM_AH + pix * 144 + khalf * 2;
            char* al = smem + SM_AL + pix * 144 + khalf * 2;
#pragma unroll 4
            for (int i = 0; i < 32; i += 2) {
                float v0 = 0.f, v1 = 0.f;
                if (ok) {
                    v0 = src[(size_t)i * NPIX] * kv;
                    v1 = src[(size_t)(i + 1) * NPIX] * kv;
                }
                __nv_bfloat16 h0 = __float2bfloat16_rn(v0);
                __nv_bfloat16 h1 = __float2bfloat16_rn(v1);
                __nv_bfloat16 l0 = __float2bfloat16_rn(v0 - __bfloat162float(h0));
                __nv_bfloat16 l1 = __float2bfloat16_rn(v1 - __bfloat162float(h1));
                __nv_bfloat162 ph; ph.x = h0; ph.y = h1;
                __nv_bfloat162 pl; pl.x = l0; pl.y = l1;
                *(__nv_bfloat162*)(ah + i * 2) = ph;
                *(__nv_bfloat162*)(al + i * 2) = pl;
            }
        }
        __syncthreads();

        // compute: 4 k-chunks x 8 n-chunks x 3 mma
        const char* AH = smem + SM_AH;
        const char* AL = smem + SM_AL;
        const uint2* b2 = (const uint2*)(smem + SM_B);
        const int aoff = (warp * 16 + gq) * 144 + tq * 4;
#pragma unroll
        for (int kc = 0; kc < 4; kc++) {
            const int o0 = aoff + kc * 32;
            uint32_t ah0 = *(const uint32_t*)(AH + o0);
            uint32_t ah1 = *(const uint32_t*)(AH + o0 + 1152);   // +8 rows
            uint32_t ah2 = *(const uint32_t*)(AH + o0 + 16);     // +8 k
            uint32_t ah3 = *(const uint32_t*)(AH + o0 + 1168);
            uint32_t al0 = *(const uint32_t*)(AL + o0);
            uint32_t al1 = *(const uint32_t*)(AL + o0 + 1152);
            uint32_t al2 = *(const uint32_t*)(AL + o0 + 16);
            uint32_t al3 = *(const uint32_t*)(AL + o0 + 1168);
#pragma unroll
            for (int nc = 0; nc < 8; nc++) {
                uint2 bh = b2[(kc * 8 + nc) * 32 + lane];
                uint2 bl = b2[((4 + kc) * 8 + nc) * 32 + lane];
                MMA16816(acc[nc], ah0, ah1, ah2, ah3, bh.x, bh.y);
                MMA16816(acc[nc], ah0, ah1, ah2, ah3, bl.x, bl.y);
                MMA16816(acc[nc], al0, al1, al2, al3, bh.x, bh.y);
            }
        }
    }

    // epilogue: C[g][tid2] layout -> pixels {pix0, pix0+8}, couts {o0, o0+1}
    const int pix0 = warp * 16 + gq;
#pragma unroll
    for (int nc = 0; nc < 8; nc++) {
        int o0 = nc * 8 + tq * 2;
        float bv0 = __ldg(bias + o0);
        float bv1 = __ldg(bias + o0 + 1);
        float v00 = acc[nc][0] + bv0;   // (pix0,   o0)
        float v01 = acc[nc][1] + bv1;   // (pix0,   o0+1)
        float v10 = acc[nc][2] + bv0;   // (pix0+8, o0)
        float v11 = acc[nc][3] + bv1;   // (pix0+8, o0+1)
        if (do_relu) {
            v00 = fmaxf(v00, 0.f); v01 = fmaxf(v01, 0.f);
            v10 = fmaxf(v10, 0.f); v11 = fmaxf(v11, 0.f);
        }
        int i00 = ((bb * Ck + o0) * Hk + h) * Wk + pix0;
        if (resid) {
            v00 += resid[i00];
            v01 += resid[i00 + NPIX];
            v10 += resid[i00 + 8];
            v11 += resid[i00 + NPIX + 8];
        }
        out[i00] = v00;
        out[i00 + NPIX] = v01;
        out[i00 + 8] = v10;
        out[i00 + NPIX + 8] = v11;
    }
}

// ---------------------------------------------------------------------------
extern "C" void kernel_launch(void* const* d_in, const int* in_sizes, int n_in,
                              void* d_out, int out_size) {
    const float* x      = (const float*)d_in[0];
    const float* edge   = (const float*)d_in[1];
    const float* w_pac1 = (const float*)d_in[2];
    const float* b_pac1 = (const float*)d_in[3];
    const float* w_pac2 = (const float*)d_in[4];
    const float* b_pac2 = (const float*)d_in[5];
    const float* w_e1   = (const float*)d_in[6];
    const float* b_e1   = (const float*)d_in[7];
    const float* w_e2   = (const float*)d_in[8];
    const float* b_e2   = (const float*)d_in[9];

    float* out_sr   = (float*)d_out;
    float* out_edge = out_sr + TENSOR;

    float *p_tmp_sr, *p_tmp_edge, *p_kern;
    uint32_t* p_wpk;
    cudaGetSymbolAddress((void**)&p_tmp_sr, g_tmp_sr);
    cudaGetSymbolAddress((void**)&p_tmp_edge, g_tmp_edge);
    cudaGetSymbolAddress((void**)&p_kern, g_kern);
    cudaGetSymbolAddress((void**)&p_wpk, g_wpk);

    cudaFuncSetAttribute(conv3x3_hmma_kernel,
                         cudaFuncAttributeMaxDynamicSharedMemorySize, CONV_SMEM);

    // fragment-packed bf16 hi/lo weights: 0=pac1, 1=pac2, 2=e1, 3=e2
    prep_weights<<<(4 * 9 * 4096 + 255) / 256, 256>>>(w_pac1, w_pac2, w_e1, w_e2);

    dim3 kgrid(Hk, Bk);
    dim3 cgrid(Hk, Bk, 2);
    const int WS = 9 * 4096;   // u32 per set

    // stage 1: z=0 pac(x, kern(edge)), z=1 plain conv(edge); both relu
    kern_field_kernel<<<kgrid, 128>>>(edge, p_kern);
    conv3x3_hmma_kernel<<<cgrid, 256, CONV_SMEM>>>(
        x,    p_kern, p_wpk + 0 * WS, b_pac1, nullptr, p_tmp_sr,
        edge,         p_wpk + 2 * WS, b_e1,   nullptr, p_tmp_edge, 1);

    // stage 2: z=0 pac(tmp_sr, kern(tmp_edge)) + x, z=1 conv(tmp_edge) + edge
    kern_field_kernel<<<kgrid, 128>>>(p_tmp_edge, p_kern);
    conv3x3_hmma_kernel<<<cgrid, 256, CONV_SMEM>>>(
        p_tmp_sr,   p_kern, p_wpk + 1 * WS, b_pac2, x,    out_sr,
        p_tmp_edge,         p_wpk + 3 * WS, b_e2,   edge, out_edge, 0);
}

// round 5
// speedup vs baseline: 1.6387x; 1.0030x over previous
#include <cuda_runtime.h>
#include <cuda_bf16.h>
#include <cstdint>
#include <math.h>

#define Bk 8
#define Ck 64
#define Hk 128
#define Wk 128
#define NPIX (Hk*Wk)                 // 16384
#define PLANE (Ck*NPIX)              // 1,048,576 per batch
#define TENSOR (Bk*PLANE)            // 8,388,608 elements

// ---------------------------------------------------------------------------
// Scratch (device globals; no allocation)
// ---------------------------------------------------------------------------
__device__ float g_tmp_sr[TENSOR];
__device__ float g_tmp_edge[TENSOR];
__device__ float g_kern[Bk * 9 * NPIX];
// packed bf16 weight fragments:
// [set 4][tap 9][kh 2][term 2][kc 2][nc 8][lane 32][reg 2] u32
__device__ uint32_t g_wpk[4 * 9 * 4096];

// ---------------------------------------------------------------------------
// mma.sync m16n8k16 row.col f32.bf16.bf16.f32 (base-target PTX, sm_80+)
// ---------------------------------------------------------------------------
#define MMA16816(c, A0, A1, A2, A3, B0, B1)                                  \
    asm volatile(                                                            \
        "mma.sync.aligned.m16n8k16.row.col.f32.bf16.bf16.f32 "               \
        "{%0,%1,%2,%3},{%4,%5,%6,%7},{%8,%9},{%0,%1,%2,%3};"                 \
        : "+f"((c)[0]), "+f"((c)[1]), "+f"((c)[2]), "+f"((c)[3])             \
        : "r"(A0), "r"(A1), "r"(A2), "r"(A3), "r"(B0), "r"(B1))

// ---------------------------------------------------------------------------
// Weight prep: w[o][c][p] -> fragment-packed bf16 hi/lo u32 words.
// ---------------------------------------------------------------------------
__global__ void prep_weights(const float* __restrict__ w0,
                             const float* __restrict__ w1,
                             const float* __restrict__ w2,
                             const float* __restrict__ w3) {
    int idx = blockIdx.x * blockDim.x + threadIdx.x;
    if (idx >= 4 * 9 * 4096) return;
    int s    = idx / 36864;
    int rem  = idx % 36864;
    int p    = rem / 4096;
    int rem2 = rem % 4096;
    int kh = (rem2 >> 11) & 1;
    int t  = (rem2 >> 10) & 1;
    int kc = (rem2 >> 9) & 1;
    int nc = (rem2 >> 6) & 7;
    int l  = (rem2 >> 1) & 31;
    int r  = rem2 & 1;

    int o = nc * 8 + (l >> 2);
    int k = kh * 32 + kc * 16 + (l & 3) * 2 + r * 8;

    const float* w = (s == 0) ? w0 : (s == 1) ? w1 : (s == 2) ? w2 : w3;
    float v0 = w[(o * 64 + k) * 9 + p];
    float v1 = w[(o * 64 + k + 1) * 9 + p];

    __nv_bfloat16 h0 = __float2bfloat16_rn(v0);
    __nv_bfloat16 h1 = __float2bfloat16_rn(v1);
    __nv_bfloat16 e0, e1;
    if (t == 0) { e0 = h0; e1 = h1; }
    else {
        e0 = __float2bfloat16_rn(v0 - __bfloat162float(h0));
        e1 = __float2bfloat16_rn(v1 - __bfloat162float(h1));
    }
    uint32_t pk = ((uint32_t)*(uint16_t*)&e1 << 16) | (uint32_t)*(uint16_t*)&e0;
    g_wpk[idx] = pk;
}

// ---------------------------------------------------------------------------
// Adaptive-kernel field: 4-row strips, 8-channel smem chunks, no div/mod.
// grid: (32, Bk), block: 256
// ---------------------------------------------------------------------------
__global__ void __launch_bounds__(256)
kern_field_kernel(const float* __restrict__ g, float* __restrict__ kout) {
    const int h0 = blockIdx.x * 4;
    const int bb = blockIdx.y;
    const int tid = threadIdx.x;

    __shared__ float s[8 * 6 * 132];

    // zero halo columns (cols 0 and 129) once
    if (tid < 96) {
        int ch = tid / 12;
        int rem = tid - ch * 12;
        int row = rem >> 1;
        int scol = (rem & 1) ? 129 : 0;
        s[(ch * 6 + row) * 132 + scol] = 0.f;
    }

    float d2[9][2];
#pragma unroll
    for (int p = 0; p < 9; p++) { d2[p][0] = 0.f; d2[p][1] = 0.f; }

    const float* gb = g + bb * PLANE;
    const int rhalf = tid >> 7;          // 0/1
    const int col   = tid & 127;

    for (int c0 = 0; c0 < 64; c0 += 8) {
        if (c0) __syncthreads();
        // stage 8 channels x 6 rows x 128 cols (+halos already zero)
#pragma unroll
        for (int ch = 0; ch < 8; ch++) {
            const float* gc = gb + (c0 + ch) * NPIX;
#pragma unroll
            for (int r2 = 0; r2 < 3; r2++) {
                int row = r2 * 2 + rhalf;            // 0..5
                int grow = h0 - 1 + row;
                float v = (grow >= 0 && grow < Hk) ? gc[grow * Wk + col] : 0.f;
                s[(ch * 6 + row) * 132 + col + 1] = v;
            }
        }
        __syncthreads();

#pragma unroll
        for (int j = 0; j < 2; j++) {
            int idx = j * 256 + tid;
            int r = idx >> 7;            // 0..3
            int w = idx & 127;
#pragma unroll
            for (int ch = 0; ch < 8; ch++) {
                const float* base = s + ch * 6 * 132;
                float ctr = base[(r + 1) * 132 + w + 1];
#pragma unroll
                for (int p = 0; p < 9; p++) {
                    float diff = base[(r + p / 3) * 132 + w + (p % 3)] - ctr;
                    d2[p][j] += diff * diff;
                }
            }
        }
    }

#pragma unroll
    for (int j = 0; j < 2; j++) {
        int idx = j * 256 + tid;
        int r = idx >> 7;
        int w = idx & 127;
        int h = h0 + r;
#pragma unroll
        for (int p = 0; p < 9; p++)
            kout[((bb * 9 + p) * Hk + h) * Wk + w] = expf(-0.5f * d2[p][j]);
    }
}

// ---------------------------------------------------------------------------
// HMMA conv, 3-buffer pipeline, 1 barrier/stage.
// Block = one image row (M=128 pix, N=64 cout), 256 thr / 8 warps.
// 18 stages: stage s -> tap p = s>>1, K-half kh = (s&1)*32.
// A layout per buf: [hi|lo] 128 rows x 80 B pitch (32 bf16 + pad).
// blockIdx.z picks conv 0 (pac) / conv 1 (plain edge).
// ---------------------------------------------------------------------------
#define SM_KS   0            // 9*128 f32 = 4608
#define SM_A    4608         // 3 bufs x 20480 (hi 10240 + lo 10240)
#define SM_B    66048        // 3 bufs x 8192
#define CONV_SMEM 90624

__global__ void __launch_bounds__(256, 2)
conv3x3_hmma_kernel(const float* __restrict__ x0,
                    const float* __restrict__ kern0,   // null => plain
                    const uint32_t* __restrict__ wt0,  // [9][4096] packed
                    const float* __restrict__ bias0,
                    const float* __restrict__ resid0,
                    float* __restrict__ out0,
                    const float* __restrict__ x1,
                    const uint32_t* __restrict__ wt1,
                    const float* __restrict__ bias1,
                    const float* __restrict__ resid1,
                    float* __restrict__ out1,
                    int do_relu) {
    extern __shared__ char smem[];
    float* k_s = (float*)(smem + SM_KS);

    const int h  = blockIdx.x;
    const int bb = blockIdx.y;
    const int z  = blockIdx.z;

    const float*    x     = z ? x1 : x0;
    const float*    kern  = z ? nullptr : kern0;
    const uint32_t* wt    = z ? wt1 : wt0;
    const float*    bias  = z ? bias1 : bias0;
    const float*    resid = z ? resid1 : resid0;
    float*          out   = z ? out1 : out0;

    const int tid  = threadIdx.x;
    const int warp = tid >> 5;
    const int lane = tid & 31;
    const int gq   = lane >> 2;
    const int tq   = lane & 3;

    // stage kern rows (or ones)
    for (int i = tid; i < 9 * 128; i += 256) {
        int p = i >> 7, pix = i & 127;
        k_s[i] = kern ? kern[((bb * 9 + p) * Hk + h) * Wk + pix] : 1.0f;
    }
    __syncthreads();

    float acc[8][4];
#pragma unroll
    for (int n = 0; n < 8; n++)
#pragma unroll
        for (int i = 0; i < 4; i++) acc[n][i] = 0.f;

    const float* xb = x + bb * PLANE;

    // staging helper (lambda-like macro avoided; inline block)
    const int spix  = tid >> 1;           // A-staging pixel
    const int g16   = (tid & 1) << 4;     // channel sub-group 0/16

#define STAGE(S, BUF) do {                                                    \
    const int p_  = (S) >> 1;                                                 \
    const int kh_ = ((S) & 1) << 5;                                           \
    /* B: 8 KB contiguous copy */                                             \
    {                                                                         \
        const uint4* src = (const uint4*)(wt + p_ * 4096 + (((S) & 1) << 11));\
        uint4* dst = (uint4*)(smem + SM_B + (BUF) * 8192);                    \
        dst[tid] = src[tid];                                                  \
        dst[tid + 256] = src[tid + 256];                                      \
    }                                                                         \
    /* A: pixel spix, 16 channels (kh_+g16 .. +15), kern folded, hi/lo */     \
    {                                                                         \
        const int dy = p_ / 3 - 1, dx = p_ % 3 - 1;                           \
        const int row = h + dy, col = spix + dx;                              \
        const bool ok = (row >= 0) && (row < Hk) && (col >= 0) && (col < Wk); \
        const float kv = k_s[p_ * 128 + spix];                                \
        const float* src = xb + (size_t)(kh_ + g16) * NPIX + row * Wk + col;  \
        char* ah = smem + SM_A + (BUF) * 20480 + spix * 80 + g16 * 2;         \
        char* al = ah + 10240;                                                \
        _Pragma("unroll")                                                     \
        for (int i = 0; i < 16; i += 2) {                                     \
            float v0 = 0.f, v1 = 0.f;                                         \
            if (ok) {                                                         \
                v0 = src[(size_t)i * NPIX] * kv;                              \
                v1 = src[(size_t)(i + 1) * NPIX] * kv;                        \
            }                                                                 \
            __nv_bfloat16 h0 = __float2bfloat16_rn(v0);                       \
            __nv_bfloat16 h1 = __float2bfloat16_rn(v1);                       \
            __nv_bfloat16 l0 = __float2bfloat16_rn(v0 - __bfloat162float(h0));\
            __nv_bfloat16 l1 = __float2bfloat16_rn(v1 - __bfloat162float(h1));\
            __nv_bfloat162 ph; ph.x = h0; ph.y = h1;                          \
            __nv_bfloat162 pl; pl.x = l0; pl.y = l1;                          \
            *(__nv_bfloat162*)(ah + i * 2) = ph;                              \
            *(__nv_bfloat162*)(al + i * 2) = pl;                              \
        }                                                                     \
    }                                                                         \
} while (0)

    // prologue: stage 0 into buf 0
    STAGE(0, 0);

    const int aoff = (warp * 16 + gq) * 80 + tq * 4;

    for (int s = 0; s < 18; s++) {
        const int cur = s % 3;
        const int nxt = (s + 1) % 3;
        __syncthreads();
        if (s + 1 < 18) STAGE(s + 1, nxt);

        // MMA on stage s from buf cur
        const char* AH = smem + SM_A + cur * 20480;
        const char* AL = AH + 10240;
        const uint2* b2 = (const uint2*)(smem + SM_B + cur * 8192);
#pragma unroll
        for (int kc = 0; kc < 2; kc++) {
            const int o0 = aoff + kc * 32;
            uint32_t ah0 = *(const uint32_t*)(AH + o0);
            uint32_t ah1 = *(const uint32_t*)(AH + o0 + 640);
            uint32_t ah2 = *(const uint32_t*)(AH + o0 + 16);
            uint32_t ah3 = *(const uint32_t*)(AH + o0 + 656);
            uint32_t al0 = *(const uint32_t*)(AL + o0);
            uint32_t al1 = *(const uint32_t*)(AL + o0 + 640);
            uint32_t al2 = *(const uint32_t*)(AL + o0 + 16);
            uint32_t al3 = *(const uint32_t*)(AL + o0 + 656);
#pragma unroll
            for (int nc = 0; nc < 8; nc++) {
                uint2 bh = b2[(kc * 8 + nc) * 32 + lane];
                uint2 bl = b2[((2 + kc) * 8 + nc) * 32 + lane];
                MMA16816(acc[nc], ah0, ah1, ah2, ah3, bh.x, bh.y);
                MMA16816(acc[nc], ah0, ah1, ah2, ah3, bl.x, bl.y);
                MMA16816(acc[nc], al0, al1, al2, al3, bh.x, bh.y);
            }
        }
    }

    // epilogue: pixels {pix0, pix0+8}, couts {o0, o0+1}
    const int pix0 = warp * 16 + gq;
#pragma unroll
    for (int nc = 0; nc < 8; nc++) {
        int o0 = nc * 8 + tq * 2;
        float bv0 = __ldg(bias + o0);
        float bv1 = __ldg(bias + o0 + 1);
        float v00 = acc[nc][0] + bv0;
        float v01 = acc[nc][1] + bv1;
        float v10 = acc[nc][2] + bv0;
        float v11 = acc[nc][3] + bv1;
        if (do_relu) {
            v00 = fmaxf(v00, 0.f); v01 = fmaxf(v01, 0.f);
            v10 = fmaxf(v10, 0.f); v11 = fmaxf(v11, 0.f);
        }
        int i00 = ((bb * Ck + o0) * Hk + h) * Wk + pix0;
        if (resid) {
            v00 += resid[i00];
            v01 += resid[i00 + NPIX];
            v10 += resid[i00 + 8];
            v11 += resid[i00 + NPIX + 8];
        }
        out[i00] = v00;
        out[i00 + NPIX] = v01;
        out[i00 + 8] = v10;
        out[i00 + NPIX + 8] = v11;
    }
}

// ---------------------------------------------------------------------------
extern "C" void kernel_launch(void* const* d_in, const int* in_sizes, int n_in,
                              void* d_out, int out_size) {
    const float* x      = (const float*)d_in[0];
    const float* edge   = (const float*)d_in[1];
    const float* w_pac1 = (const float*)d_in[2];
    const float* b_pac1 = (const float*)d_in[3];
    const float* w_pac2 = (const float*)d_in[4];
    const float* b_pac2 = (const float*)d_in[5];
    const float* w_e1   = (const float*)d_in[6];
    const float* b_e1   = (const float*)d_in[7];
    const float* w_e2   = (const float*)d_in[8];
    const float* b_e2   = (const float*)d_in[9];

    float* out_sr   = (float*)d_out;
    float* out_edge = out_sr + TENSOR;

    float *p_tmp_sr, *p_tmp_edge, *p_kern;
    uint32_t* p_wpk;
    cudaGetSymbolAddress((void**)&p_tmp_sr, g_tmp_sr);
    cudaGetSymbolAddress((void**)&p_tmp_edge, g_tmp_edge);
    cudaGetSymbolAddress((void**)&p_kern, g_kern);
    cudaGetSymbolAddress((void**)&p_wpk, g_wpk);

    cudaFuncSetAttribute(conv3x3_hmma_kernel,
                         cudaFuncAttributeMaxDynamicSharedMemorySize, CONV_SMEM);

    prep_weights<<<(4 * 9 * 4096 + 255) / 256, 256>>>(w_pac1, w_pac2, w_e1, w_e2);

    dim3 kgrid(32, Bk);
    dim3 cgrid(Hk, Bk, 2);
    const int WS = 9 * 4096;

    // stage 1: z=0 pac(x, kern(edge)), z=1 plain conv(edge); both relu
    kern_field_kernel<<<kgrid, 256>>>(edge, p_kern);
    conv3x3_hmma_kernel<<<cgrid, 256, CONV_SMEM>>>(
        x,    p_kern, p_wpk + 0 * WS, b_pac1, nullptr, p_tmp_sr,
        edge,         p_wpk + 2 * WS, b_e1,   nullptr, p_tmp_edge, 1);

    // stage 2: z=0 pac(tmp_sr, kern(tmp_edge)) + x, z=1 conv(tmp_edge) + edge
    kern_field_kernel<<<kgrid, 256>>>(p_tmp_edge, p_kern);
    conv3x3_hmma_kernel<<<cgrid, 256, CONV_SMEM>>>(
        p_tmp_sr,   p_kern, p_wpk + 1 * WS, b_pac2, x,    out_sr,
        p_tmp_edge,         p_wpk + 3 * WS, b_e2,   edge, out_edge, 0);
}

// round 6
// speedup vs baseline: 1.7625x; 1.0755x over previous
#include <cuda_runtime.h>
#include <cuda_bf16.h>
#include <cstdint>
#include <math.h>

#define Bk 8
#define Ck 64
#define Hk 128
#define Wk 128
#define NPIX (Hk*Wk)                 // 16384
#define PLANE (Ck*NPIX)              // 1,048,576 per batch
#define TENSOR (Bk*PLANE)            // 8,388,608 elements

// ---------------------------------------------------------------------------
// Scratch (device globals; no allocation)
// ---------------------------------------------------------------------------
__device__ float g_tmp_sr[TENSOR];
__device__ float g_tmp_edge[TENSOR];
__device__ float g_kern[Bk * 9 * NPIX];
// packed bf16 weight fragments:
// [set 4][tap 9][kh 2][kc 2][nc 8][lane 32][term 2][reg 2] u32
__device__ uint32_t g_wpk[4 * 9 * 4096];

// ---------------------------------------------------------------------------
// PTX primitives (base-target: sm_75+/sm_80+)
// ---------------------------------------------------------------------------
#define MMA16816(c, A0, A1, A2, A3, B0, B1)                                  \
    asm volatile(                                                            \
        "mma.sync.aligned.m16n8k16.row.col.f32.bf16.bf16.f32 "               \
        "{%0,%1,%2,%3},{%4,%5,%6,%7},{%8,%9},{%0,%1,%2,%3};"                 \
        : "+f"((c)[0]), "+f"((c)[1]), "+f"((c)[2]), "+f"((c)[3])             \
        : "r"(A0), "r"(A1), "r"(A2), "r"(A3), "r"(B0), "r"(B1))

#define LDMATRIX_X4(r0, r1, r2, r3, addr)                                    \
    asm volatile(                                                            \
        "ldmatrix.sync.aligned.m8n8.x4.shared.b16 {%0,%1,%2,%3}, [%4];"      \
        : "=r"(r0), "=r"(r1), "=r"(r2), "=r"(r3) : "r"(addr))

__device__ __forceinline__ uint32_t smem_u32(const void* p) {
    uint32_t a;
    asm("{ .reg .u64 t; cvta.to.shared.u64 t, %1; cvt.u32.u64 %0, t; }"
        : "=r"(a) : "l"(p));
    return a;
}

// ---------------------------------------------------------------------------
// Weight prep: w[o][c][p] -> fragment-packed bf16 hi/lo u32 words.
// Word layout per tap: [kh][kc][nc][lane][term][reg]
// ---------------------------------------------------------------------------
__global__ void prep_weights(const float* __restrict__ w0,
                             const float* __restrict__ w1,
                             const float* __restrict__ w2,
                             const float* __restrict__ w3) {
    int idx = blockIdx.x * blockDim.x + threadIdx.x;
    if (idx >= 4 * 9 * 4096) return;
    int s    = idx / 36864;
    int rem  = idx % 36864;
    int p    = rem / 4096;
    int rem2 = rem % 4096;
    int kh   = (rem2 >> 11) & 1;
    int kc   = (rem2 >> 10) & 1;
    int nc   = (rem2 >> 7) & 7;
    int l    = (rem2 >> 2) & 31;
    int t    = (rem2 >> 1) & 1;
    int r    = rem2 & 1;

    int o = nc * 8 + (l >> 2);
    int k = kh * 32 + kc * 16 + (l & 3) * 2 + r * 8;

    const float* w = (s == 0) ? w0 : (s == 1) ? w1 : (s == 2) ? w2 : w3;
    float v0 = w[(o * 64 + k) * 9 + p];
    float v1 = w[(o * 64 + k + 1) * 9 + p];

    __nv_bfloat16 h0 = __float2bfloat16_rn(v0);
    __nv_bfloat16 h1 = __float2bfloat16_rn(v1);
    __nv_bfloat16 e0, e1;
    if (t == 0) { e0 = h0; e1 = h1; }
    else {
        e0 = __float2bfloat16_rn(v0 - __bfloat162float(h0));
        e1 = __float2bfloat16_rn(v1 - __bfloat162float(h1));
    }
    uint32_t pk = ((uint32_t)*(uint16_t*)&e1 << 16) | (uint32_t)*(uint16_t*)&e0;
    g_wpk[idx] = pk;
}

// ---------------------------------------------------------------------------
// Adaptive-kernel field: one row per block, 8-channel smem chunks.
// grid: (Hk, Bk), block: 128
// ---------------------------------------------------------------------------
__global__ void __launch_bounds__(128)
kern_field_kernel(const float* __restrict__ g, float* __restrict__ kout) {
    const int h  = blockIdx.x;
    const int bb = blockIdx.y;
    const int w  = threadIdx.x;

    __shared__ float s[8][3][132];

    float d2[9];
#pragma unroll
    for (int p = 0; p < 9; p++) d2[p] = 0.f;

    const float* gb = g + bb * PLANE;

    for (int c0 = 0; c0 < 64; c0 += 8) {
        if (c0) __syncthreads();
#pragma unroll
        for (int ch = 0; ch < 8; ch++) {
            const float* gc = gb + (c0 + ch) * NPIX;
#pragma unroll
            for (int r = 0; r < 3; r++) {
                int row = h + r - 1;
                s[ch][r][w + 1] = (row >= 0 && row < Hk) ? gc[row * Wk + w] : 0.f;
                if (w == 0)   s[ch][r][0]   = 0.f;
                if (w == 127) s[ch][r][129] = 0.f;
            }
        }
        __syncthreads();
#pragma unroll
        for (int ch = 0; ch < 8; ch++) {
            float ctr = s[ch][1][w + 1];
#pragma unroll
            for (int p = 0; p < 9; p++) {
                float diff = s[ch][p / 3][w + (p % 3)] - ctr;
                d2[p] += diff * diff;
            }
        }
    }

#pragma unroll
    for (int p = 0; p < 9; p++)
        kout[((bb * 9 + p) * Hk + h) * Wk + w] = expf(-0.5f * d2[p]);
}

// ---------------------------------------------------------------------------
// HMMA conv, double-buffered, 1 barrier/stage, ldmatrix A + LDS.128 B.
// Block = one image row (M=128 pix, N=64 cout), 256 thr / 8 warps.
// 18 stages: tap p = s>>1, K-half kh = (s&1)*32.
// A per buf: [hi|lo] 128 rows x 80 B pitch.
// ---------------------------------------------------------------------------
#define SM_KS   0            // 9*128 f32 = 4608
#define SM_A    4608         // 2 bufs x 20480 (hi 10240 + lo 10240)
#define SM_B    45568        // 2 bufs x 8192
#define CONV_SMEM 61952

__global__ void __launch_bounds__(256, 3)
conv3x3_hmma_kernel(const float* __restrict__ x0,
                    const float* __restrict__ kern0,   // null => plain
                    const uint32_t* __restrict__ wt0,
                    const float* __restrict__ bias0,
                    const float* __restrict__ resid0,
                    float* __restrict__ out0,
                    const float* __restrict__ x1,
                    const uint32_t* __restrict__ wt1,
                    const float* __restrict__ bias1,
                    const float* __restrict__ resid1,
                    float* __restrict__ out1,
                    int do_relu) {
    extern __shared__ char smem[];
    float* k_s = (float*)(smem + SM_KS);
    const uint32_t sb = smem_u32(smem);

    const int h  = blockIdx.x;
    const int bb = blockIdx.y;
    const int z  = blockIdx.z;

    const float*    x     = z ? x1 : x0;
    const float*    kern  = z ? nullptr : kern0;
    const uint32_t* wt    = z ? wt1 : wt0;
    const float*    bias  = z ? bias1 : bias0;
    const float*    resid = z ? resid1 : resid0;
    float*          out   = z ? out1 : out0;

    const int tid  = threadIdx.x;
    const int warp = tid >> 5;
    const int lane = tid & 31;
    const int gq   = lane >> 2;
    const int tq   = lane & 3;

    // stage kern rows (or ones)
    for (int i = tid; i < 9 * 128; i += 256) {
        int p = i >> 7, pix = i & 127;
        k_s[i] = kern ? kern[((bb * 9 + p) * Hk + h) * Wk + pix] : 1.0f;
    }
    __syncthreads();

    float acc[8][4];
#pragma unroll
    for (int n = 0; n < 8; n++)
#pragma unroll
        for (int i = 0; i < 4; i++) acc[n][i] = 0.f;

    const float* xb = x + bb * PLANE;

    const int spix = tid >> 1;           // A-staging pixel
    const int g16  = (tid & 1) << 4;     // channel sub-group 0/16

#define STAGE(S, BUF) do {                                                    \
    const int p_  = (S) >> 1;                                                 \
    const int kh_ = ((S) & 1) << 5;                                           \
    /* B: 8 KB contiguous copy */                                             \
    {                                                                         \
        const uint4* src = (const uint4*)(wt + p_ * 4096 + (((S) & 1) << 11));\
        uint4* dst = (uint4*)(smem + SM_B + (BUF) * 8192);                    \
        dst[tid] = src[tid];                                                  \
        dst[tid + 256] = src[tid + 256];                                      \
    }                                                                         \
    /* A: pixel spix, 16 channels, kern folded, hi/lo split */                \
    {                                                                         \
        const int dy = p_ / 3 - 1, dx = p_ % 3 - 1;                           \
        const int row = h + dy, col = spix + dx;                              \
        const bool ok = (row >= 0) && (row < Hk) && (col >= 0) && (col < Wk); \
        const float kv = k_s[p_ * 128 + spix];                                \
        const float* src = xb + (size_t)(kh_ + g16) * NPIX + row * Wk + col;  \
        char* ah = smem + SM_A + (BUF) * 20480 + spix * 80 + g16 * 2;         \
        char* al = ah + 10240;                                                \
        _Pragma("unroll")                                                     \
        for (int i = 0; i < 16; i += 2) {                                     \
            float v0 = 0.f, v1 = 0.f;                                         \
            if (ok) {                                                         \
                v0 = src[(size_t)i * NPIX] * kv;                              \
                v1 = src[(size_t)(i + 1) * NPIX] * kv;                        \
            }                                                                 \
            __nv_bfloat16 h0 = __float2bfloat16_rn(v0);                       \
            __nv_bfloat16 h1 = __float2bfloat16_rn(v1);                       \
            __nv_bfloat16 l0 = __float2bfloat16_rn(v0 - __bfloat162float(h0));\
            __nv_bfloat16 l1 = __float2bfloat16_rn(v1 - __bfloat162float(h1));\
            __nv_bfloat162 ph; ph.x = h0; ph.y = h1;                          \
            __nv_bfloat162 pl; pl.x = l0; pl.y = l1;                          \
            *(__nv_bfloat162*)(ah + i * 2) = ph;                              \
            *(__nv_bfloat162*)(al + i * 2) = pl;                              \
        }                                                                     \
    }                                                                         \
} while (0)

    // prologue: stage 0 into buf 0
    STAGE(0, 0);

    // ldmatrix per-lane address: rows 0-15 (k 0-7) for lanes 0-15,
    // rows 0-15 (k 8-15) for lanes 16-31
    const uint32_t lmoff =
        (uint32_t)((warp * 16 + (lane & 15)) * 80 + ((lane >> 4) << 4));

    for (int s = 0; s < 18; s++) {
        const int cur = s & 1;
        __syncthreads();
        if (s + 1 < 18) STAGE(s + 1, cur ^ 1);

        const uint32_t aA = sb + SM_A + cur * 20480 + lmoff;
        const uint4* b4 = (const uint4*)(smem + SM_B + cur * 8192);
#pragma unroll
        for (int kc = 0; kc < 2; kc++) {
            uint32_t ah0, ah1, ah2, ah3, al0, al1, al2, al3;
            LDMATRIX_X4(ah0, ah1, ah2, ah3, aA + kc * 32);
            LDMATRIX_X4(al0, al1, al2, al3, aA + kc * 32 + 10240);
#pragma unroll
            for (int nc = 0; nc < 8; nc++) {
                uint4 bv = b4[(kc * 8 + nc) * 32 + lane];
                MMA16816(acc[nc], ah0, ah1, ah2, ah3, bv.x, bv.y);
                MMA16816(acc[nc], ah0, ah1, ah2, ah3, bv.z, bv.w);
                MMA16816(acc[nc], al0, al1, al2, al3, bv.x, bv.y);
            }
        }
    }

    // epilogue: pixels {pix0, pix0+8}, couts {o0, o0+1}
    const int pix0 = warp * 16 + gq;
#pragma unroll
    for (int nc = 0; nc < 8; nc++) {
        int o0 = nc * 8 + tq * 2;
        float bv0 = __ldg(bias + o0);
        float bv1 = __ldg(bias + o0 + 1);
        float v00 = acc[nc][0] + bv0;
        float v01 = acc[nc][1] + bv1;
        float v10 = acc[nc][2] + bv0;
        float v11 = acc[nc][3] + bv1;
        if (do_relu) {
            v00 = fmaxf(v00, 0.f); v01 = fmaxf(v01, 0.f);
            v10 = fmaxf(v10, 0.f); v11 = fmaxf(v11, 0.f);
        }
        int i00 = ((bb * Ck + o0) * Hk + h) * Wk + pix0;
        if (resid) {
            v00 += resid[i00];
            v01 += resid[i00 + NPIX];
            v10 += resid[i00 + 8];
            v11 += resid[i00 + NPIX + 8];
        }
        out[i00] = v00;
        out[i00 + NPIX] = v01;
        out[i00 + 8] = v10;
        out[i00 + NPIX + 8] = v11;
    }
}

// ---------------------------------------------------------------------------
extern "C" void kernel_launch(void* const* d_in, const int* in_sizes, int n_in,
                              void* d_out, int out_size) {
    const float* x      = (const float*)d_in[0];
    const float* edge   = (const float*)d_in[1];
    const float* w_pac1 = (const float*)d_in[2];
    const float* b_pac1 = (const float*)d_in[3];
    const float* w_pac2 = (const float*)d_in[4];
    const float* b_pac2 = (const float*)d_in[5];
    const float* w_e1   = (const float*)d_in[6];
    const float* b_e1   = (const float*)d_in[7];
    const float* w_e2   = (const float*)d_in[8];
    const float* b_e2   = (const float*)d_in[9];

    float* out_sr   = (float*)d_out;
    float* out_edge = out_sr + TENSOR;

    float *p_tmp_sr, *p_tmp_edge, *p_kern;
    uint32_t* p_wpk;
    cudaGetSymbolAddress((void**)&p_tmp_sr, g_tmp_sr);
    cudaGetSymbolAddress((void**)&p_tmp_edge, g_tmp_edge);
    cudaGetSymbolAddress((void**)&p_kern, g_kern);
    cudaGetSymbolAddress((void**)&p_wpk, g_wpk);

    cudaFuncSetAttribute(conv3x3_hmma_kernel,
                         cudaFuncAttributeMaxDynamicSharedMemorySize, CONV_SMEM);

    prep_weights<<<(4 * 9 * 4096 + 255) / 256, 256>>>(w_pac1, w_pac2, w_e1, w_e2);

    dim3 kgrid(Hk, Bk);
    dim3 cgrid(Hk, Bk, 2);
    const int WS = 9 * 4096;

    // stage 1: z=0 pac(x, kern(edge)), z=1 plain conv(edge); both relu
    kern_field_kernel<<<kgrid, 128>>>(edge, p_kern);
    conv3x3_hmma_kernel<<<cgrid, 256, CONV_SMEM>>>(
        x,    p_kern, p_wpk + 0 * WS, b_pac1, nullptr, p_tmp_sr,
        edge,         p_wpk + 2 * WS, b_e1,   nullptr, p_tmp_edge, 1);

    // stage 2: z=0 pac(tmp_sr, kern(tmp_edge)) + x, z=1 conv(tmp_edge) + edge
    kern_field_kernel<<<kgrid, 128>>>(p_tmp_edge, p_kern);
    conv3x3_hmma_kernel<<<cgrid, 256, CONV_SMEM>>>(
        p_tmp_sr,   p_kern, p_wpk + 1 * WS, b_pac2, x,    out_sr,
        p_tmp_edge,         p_wpk + 3 * WS, b_e2,   edge, out_edge, 0);
}

// round 7
// speedup vs baseline: 2.0556x; 1.1663x over previous
#include <cuda_runtime.h>
#include <cuda_bf16.h>
#include <cstdint>
#include <math.h>

#define Bk 8
#define Ck 64
#define Hk 128
#define Wk 128
#define NPIX (Hk*Wk)                 // 16384
#define PLANE (Ck*NPIX)              // 1,048,576 per batch
#define TENSOR (Bk*PLANE)            // 8,388,608 elements

// ---------------------------------------------------------------------------
// Scratch (device globals; no allocation)
// ---------------------------------------------------------------------------
__device__ float g_tmp_sr[TENSOR];
__device__ float g_tmp_edge[TENSOR];
__device__ float g_kern[Bk * 9 * NPIX];
__device__ float g_fields[Bk * 5 * NPIX];   // sq, dot(0,1), dot(1,-1), dot(1,0), dot(1,1)
// packed bf16 weight fragments:
// [set 4][tap 9][kh 2][kc 2][nc 8][lane 32][term 2][reg 2] u32
__device__ uint32_t g_wpk[4 * 9 * 4096];

// ---------------------------------------------------------------------------
// PTX primitives (base-target: sm_75+/sm_80+)
// ---------------------------------------------------------------------------
#define MMA16816(c, A0, A1, A2, A3, B0, B1)                                  \
    asm volatile(                                                            \
        "mma.sync.aligned.m16n8k16.row.col.f32.bf16.bf16.f32 "               \
        "{%0,%1,%2,%3},{%4,%5,%6,%7},{%8,%9},{%0,%1,%2,%3};"                 \
        : "+f"((c)[0]), "+f"((c)[1]), "+f"((c)[2]), "+f"((c)[3])             \
        : "r"(A0), "r"(A1), "r"(A2), "r"(A3), "r"(B0), "r"(B1))

#define LDMATRIX_X4(r0, r1, r2, r3, addr)                                    \
    asm volatile(                                                            \
        "ldmatrix.sync.aligned.m8n8.x4.shared.b16 {%0,%1,%2,%3}, [%4];"      \
        : "=r"(r0), "=r"(r1), "=r"(r2), "=r"(r3) : "r"(addr))

__device__ __forceinline__ uint32_t smem_u32(const void* p) {
    uint32_t a;
    asm("{ .reg .u64 t; cvta.to.shared.u64 t, %1; cvt.u32.u64 %0, t; }"
        : "=r"(a) : "l"(p));
    return a;
}

// ---------------------------------------------------------------------------
// Weight prep (RN split, done once): [kh][kc][nc][lane][term][reg]
// ---------------------------------------------------------------------------
__global__ void prep_weights(const float* __restrict__ w0,
                             const float* __restrict__ w1,
                             const float* __restrict__ w2,
                             const float* __restrict__ w3) {
    int idx = blockIdx.x * blockDim.x + threadIdx.x;
    if (idx >= 4 * 9 * 4096) return;
    int s    = idx / 36864;
    int rem  = idx % 36864;
    int p    = rem / 4096;
    int rem2 = rem % 4096;
    int kh   = (rem2 >> 11) & 1;
    int kc   = (rem2 >> 10) & 1;
    int nc   = (rem2 >> 7) & 7;
    int l    = (rem2 >> 2) & 31;
    int t    = (rem2 >> 1) & 1;
    int r    = rem2 & 1;

    int o = nc * 8 + (l >> 2);
    int k = kh * 32 + kc * 16 + (l & 3) * 2 + r * 8;

    const float* w = (s == 0) ? w0 : (s == 1) ? w1 : (s == 2) ? w2 : w3;
    float v0 = w[(o * 64 + k) * 9 + p];
    float v1 = w[(o * 64 + k + 1) * 9 + p];

    __nv_bfloat16 h0 = __float2bfloat16_rn(v0);
    __nv_bfloat16 h1 = __float2bfloat16_rn(v1);
    __nv_bfloat16 e0, e1;
    if (t == 0) { e0 = h0; e1 = h1; }
    else {
        e0 = __float2bfloat16_rn(v0 - __bfloat162float(h0));
        e1 = __float2bfloat16_rn(v1 - __bfloat162float(h1));
    }
    uint32_t pk = ((uint32_t)*(uint16_t*)&e1 << 16) | (uint32_t)*(uint16_t*)&e0;
    g_wpk[idx] = pk;
}

// ---------------------------------------------------------------------------
// Pass A: per-pixel fields. sq = sum g^2; dot(0,1); dot(1,e) e=-1,0,1 where
// dot(1,e)[h][w] = sum_c g[c,h,w]*g[c,h+1,w+e]. grid (Hk,Bk), 128 thr.
// ---------------------------------------------------------------------------
__global__ void __launch_bounds__(128)
field_kernel(const float* __restrict__ g, float* __restrict__ F) {
    const int h  = blockIdx.x;
    const int bb = blockIdx.y;
    const int w  = threadIdx.x;

    __shared__ float s[8][2][132];   // [ch][row h / h+1][col -1..129 -> idx 0..130]

    float sq = 0.f, d01 = 0.f, d1m = 0.f, d10 = 0.f, d1p = 0.f;

    const float* gb = g + bb * PLANE;
    const bool row1ok = (h + 1 < Hk);

    for (int c0 = 0; c0 < 64; c0 += 8) {
        if (c0) __syncthreads();
#pragma unroll
        for (int ch = 0; ch < 8; ch++) {
            const float* gc = gb + (c0 + ch) * NPIX;
            s[ch][0][w + 1] = gc[h * Wk + w];
            s[ch][1][w + 1] = row1ok ? gc[(h + 1) * Wk + w] : 0.f;
            if (w == 0) {
                s[ch][0][0] = 0.f; s[ch][1][0] = 0.f;
                s[ch][0][129] = 0.f; s[ch][1][129] = 0.f;
            }
        }
        __syncthreads();
#pragma unroll
        for (int ch = 0; ch < 8; ch++) {
            float c  = s[ch][0][w + 1];
            float r  = s[ch][0][w + 2];
            float bl = s[ch][1][w];
            float bc = s[ch][1][w + 1];
            float br = s[ch][1][w + 2];
            sq  += c * c;
            d01 += c * r;
            d1m += c * bl;
            d10 += c * bc;
            d1p += c * br;
        }
    }

    float* Fb = F + bb * 5 * NPIX + h * Wk + w;
    Fb[0 * NPIX] = sq;
    Fb[1 * NPIX] = d01;
    Fb[2 * NPIX] = d1m;
    Fb[3 * NPIX] = d10;
    Fb[4 * NPIX] = d1p;
}

// ---------------------------------------------------------------------------
// Pass B: assemble kern[b][p][h][w] = exp(-0.5*(sq_nb + sq_c - 2*dot)).
// grid (Hk, Bk), 128 thr.
// ---------------------------------------------------------------------------
__global__ void __launch_bounds__(128)
kern_assemble_kernel(const float* __restrict__ F, float* __restrict__ kout) {
    const int h  = blockIdx.x;
    const int bb = blockIdx.y;
    const int w  = threadIdx.x;

    const float* Fb = F + bb * 5 * NPIX;
    const float sqc = Fb[h * Wk + w];

    float* ko = kout + (bb * 9) * NPIX + h * Wk + w;

#pragma unroll
    for (int p = 0; p < 9; p++) {
        if (p == 4) { ko[4 * NPIX] = 1.0f; continue; }
        const int dy = p / 3 - 1, dx = p % 3 - 1;
        const int row = h + dy, col = w + dx;
        const bool inb = (row >= 0) && (row < Hk) && (col >= 0) && (col < Wk);
        float sqn = 0.f, dot = 0.f;
        if (inb) {
            sqn = Fb[row * Wk + col];
            if (dy == 0) {
                // dx = +1: dot(0,1)[h][w]; dx = -1: dot(0,1)[h][w-1]
                dot = (dx == 1) ? Fb[NPIX + h * Wk + w]
                                : Fb[NPIX + h * Wk + (w - 1)];
            } else if (dy == 1) {
                dot = Fb[(3 + dx) * NPIX + h * Wk + w];
            } else { // dy == -1: dot(1,-dx)[h-1][w+dx]
                dot = Fb[(3 - dx) * NPIX + (h - 1) * Wk + col];
            }
        }
        float d2 = sqn + sqc - 2.f * dot;
        ko[p * NPIX] = __expf(-0.5f * d2);
    }
}

// ---------------------------------------------------------------------------
// HMMA conv, double-buffered, 1 barrier/stage, ldmatrix A + LDS.128 B.
// Block = one image row (M=128 pix, N=64 cout), 256 thr / 8 warps.
// 18 stages: tap p = s>>1, K-half kh = (s&1)*32.
// A per buf: [hi|lo] 128 rows x 80 B pitch.
// ---------------------------------------------------------------------------
#define SM_KS   0            // 9*128 f32 = 4608
#define SM_A    4608         // 2 bufs x 20480 (hi 10240 + lo 10240)
#define SM_B    45568        // 2 bufs x 8192
#define CONV_SMEM 61952

__global__ void __launch_bounds__(256, 3)
conv3x3_hmma_kernel(const float* __restrict__ x0,
                    const float* __restrict__ kern0,   // null => plain
                    const uint32_t* __restrict__ wt0,
                    const float* __restrict__ bias0,
                    const float* __restrict__ resid0,
                    float* __restrict__ out0,
                    const float* __restrict__ x1,
                    const uint32_t* __restrict__ wt1,
                    const float* __restrict__ bias1,
                    const float* __restrict__ resid1,
                    float* __restrict__ out1,
                    int do_relu) {
    extern __shared__ char smem[];
    float* k_s = (float*)(smem + SM_KS);
    const uint32_t sb = smem_u32(smem);

    const int h  = blockIdx.x;
    const int bb = blockIdx.y;
    const int z  = blockIdx.z;

    const float*    x     = z ? x1 : x0;
    const float*    kern  = z ? nullptr : kern0;
    const uint32_t* wt    = z ? wt1 : wt0;
    const float*    bias  = z ? bias1 : bias0;
    const float*    resid = z ? resid1 : resid0;
    float*          out   = z ? out1 : out0;

    const int tid  = threadIdx.x;
    const int warp = tid >> 5;
    const int lane = tid & 31;
    const int gq   = lane >> 2;
    const int tq   = lane & 3;

    // stage kern rows (or ones)
    for (int i = tid; i < 9 * 128; i += 256) {
        int p = i >> 7, pix = i & 127;
        k_s[i] = kern ? kern[((bb * 9 + p) * Hk + h) * Wk + pix] : 1.0f;
    }
    __syncthreads();

    float acc[8][4];
#pragma unroll
    for (int n = 0; n < 8; n++)
#pragma unroll
        for (int i = 0; i < 4; i++) acc[n][i] = 0.f;

    const float* xb = x + bb * PLANE;

    const int spix = tid >> 1;           // A-staging pixel
    const int g16  = (tid & 1) << 4;     // channel sub-group 0/16

// hi term = bit-truncated bf16 (PRMT pack), lo = exact residual, RN to bf16.
#define STAGE(S, BUF) do {                                                    \
    const int p_  = (S) >> 1;                                                 \
    const int kh_ = ((S) & 1) << 5;                                           \
    /* B: 8 KB contiguous copy */                                             \
    {                                                                         \
        const uint4* src = (const uint4*)(wt + p_ * 4096 + (((S) & 1) << 11));\
        uint4* dst = (uint4*)(smem + SM_B + (BUF) * 8192);                    \
        dst[tid] = src[tid];                                                  \
        dst[tid + 256] = src[tid + 256];                                      \
    }                                                                         \
    /* A: pixel spix, 16 channels, kern folded, trunc hi / residual lo */     \
    {                                                                         \
        const int dy = p_ / 3 - 1, dx = p_ % 3 - 1;                           \
        const int row = h + dy, col = spix + dx;                              \
        const bool ok = (row >= 0) && (row < Hk) && (col >= 0) && (col < Wk); \
        const float kv = k_s[p_ * 128 + spix];                                \
        const float* src = xb + (size_t)(kh_ + g16) * NPIX + row * Wk + col;  \
        char* ah = smem + SM_A + (BUF) * 20480 + spix * 80 + g16 * 2;         \
        char* al = ah + 10240;                                                \
        _Pragma("unroll")                                                     \
        for (int i = 0; i < 16; i += 2) {                                     \
            float v0 = 0.f, v1 = 0.f;                                         \
            if (ok) {                                                         \
                v0 = src[(size_t)i * NPIX] * kv;                              \
                v1 = src[(size_t)(i + 1) * NPIX] * kv;                        \
            }                                                                 \
            uint32_t u0 = __float_as_uint(v0);                                \
            uint32_t u1 = __float_as_uint(v1);                                \
            uint32_t hipk = __byte_perm(u0, u1, 0x7632);                      \
            float lo0 = v0 - __uint_as_float(u0 & 0xffff0000u);               \
            float lo1 = v1 - __uint_as_float(u1 & 0xffff0000u);               \
            float2 lf; lf.x = lo0; lf.y = lo1;                                \
            __nv_bfloat162 lp = __float22bfloat162_rn(lf);                    \
            *(uint32_t*)(ah + i * 2) = hipk;                                  \
            *(__nv_bfloat162*)(al + i * 2) = lp;                              \
        }                                                                     \
    }                                                                         \
} while (0)

    // prologue: stage 0 into buf 0
    STAGE(0, 0);

    const uint32_t lmoff =
        (uint32_t)((warp * 16 + (lane & 15)) * 80 + ((lane >> 4) << 4));

    for (int s = 0; s < 18; s++) {
        const int cur = s & 1;
        __syncthreads();
        if (s + 1 < 18) STAGE(s + 1, cur ^ 1);

        const uint32_t aA = sb + SM_A + cur * 20480 + lmoff;
        const uint4* b4 = (const uint4*)(smem + SM_B + cur * 8192);
#pragma unroll
        for (int kc = 0; kc < 2; kc++) {
            uint32_t ah0, ah1, ah2, ah3, al0, al1, al2, al3;
            LDMATRIX_X4(ah0, ah1, ah2, ah3, aA + kc * 32);
            LDMATRIX_X4(al0, al1, al2, al3, aA + kc * 32 + 10240);
#pragma unroll
            for (int nc = 0; nc < 8; nc++) {
                uint4 bv = b4[(kc * 8 + nc) * 32 + lane];
                MMA16816(acc[nc], ah0, ah1, ah2, ah3, bv.x, bv.y);
                MMA16816(acc[nc], ah0, ah1, ah2, ah3, bv.z, bv.w);
                MMA16816(acc[nc], al0, al1, al2, al3, bv.x, bv.y);
            }
        }
    }

    // epilogue
    const int pix0 = warp * 16 + gq;
#pragma unroll
    for (int nc = 0; nc < 8; nc++) {
        int o0 = nc * 8 + tq * 2;
        float bv0 = __ldg(bias + o0);
        float bv1 = __ldg(bias + o0 + 1);
        float v00 = acc[nc][0] + bv0;
        float v01 = acc[nc][1] + bv1;
        float v10 = acc[nc][2] + bv0;
        float v11 = acc[nc][3] + bv1;
        if (do_relu) {
            v00 = fmaxf(v00, 0.f); v01 = fmaxf(v01, 0.f);
            v10 = fmaxf(v10, 0.f); v11 = fmaxf(v11, 0.f);
        }
        int i00 = ((bb * Ck + o0) * Hk + h) * Wk + pix0;
        if (resid) {
            v00 += resid[i00];
            v01 += resid[i00 + NPIX];
            v10 += resid[i00 + 8];
            v11 += resid[i00 + NPIX + 8];
        }
        out[i00] = v00;
        out[i00 + NPIX] = v01;
        out[i00 + 8] = v10;
        out[i00 + NPIX + 8] = v11;
    }
}

// ---------------------------------------------------------------------------
extern "C" void kernel_launch(void* const* d_in, const int* in_sizes, int n_in,
                              void* d_out, int out_size) {
    const float* x      = (const float*)d_in[0];
    const float* edge   = (const float*)d_in[1];
    const float* w_pac1 = (const float*)d_in[2];
    const float* b_pac1 = (const float*)d_in[3];
    const float* w_pac2 = (const float*)d_in[4];
    const float* b_pac2 = (const float*)d_in[5];
    const float* w_e1   = (const float*)d_in[6];
    const float* b_e1   = (const float*)d_in[7];
    const float* w_e2   = (const float*)d_in[8];
    const float* b_e2   = (const float*)d_in[9];

    float* out_sr   = (float*)d_out;
    float* out_edge = out_sr + TENSOR;

    float *p_tmp_sr, *p_tmp_edge, *p_kern, *p_fields;
    uint32_t* p_wpk;
    cudaGetSymbolAddress((void**)&p_tmp_sr, g_tmp_sr);
    cudaGetSymbolAddress((void**)&p_tmp_edge, g_tmp_edge);
    cudaGetSymbolAddress((void**)&p_kern, g_kern);
    cudaGetSymbolAddress((void**)&p_fields, g_fields);
    cudaGetSymbolAddress((void**)&p_wpk, g_wpk);

    cudaFuncSetAttribute(conv3x3_hmma_kernel,
                         cudaFuncAttributeMaxDynamicSharedMemorySize, CONV_SMEM);

    prep_weights<<<(4 * 9 * 4096 + 255) / 256, 256>>>(w_pac1, w_pac2, w_e1, w_e2);

    dim3 kgrid(Hk, Bk);
    dim3 cgrid(Hk, Bk, 2);
    const int WS = 9 * 4096;

    // stage 1: kern(edge); z=0 pac(x), z=1 plain conv(edge); both relu
    field_kernel<<<kgrid, 128>>>(edge, p_fields);
    kern_assemble_kernel<<<kgrid, 128>>>(p_fields, p_kern);
    conv3x3_hmma_kernel<<<cgrid, 256, CONV_SMEM>>>(
        x,    p_kern, p_wpk + 0 * WS, b_pac1, nullptr, p_tmp_sr,
        edge,         p_wpk + 2 * WS, b_e1,   nullptr, p_tmp_edge, 1);

    // stage 2: kern(tmp_edge); z=0 pac(tmp_sr)+x, z=1 conv(tmp_edge)+edge
    field_kernel<<<kgrid, 128>>>(p_tmp_edge, p_fields);
    kern_assemble_kernel<<<kgrid, 128>>>(p_fields, p_kern);
    conv3x3_hmma_kernel<<<cgrid, 256, CONV_SMEM>>>(
        p_tmp_sr,   p_kern, p_wpk + 1 * WS, b_pac2, x,    out_sr,
        p_tmp_edge,         p_wpk + 3 * WS, b_e2,   edge, out_edge, 0);
}

// round 8
// speedup vs baseline: 2.3361x; 1.1365x over previous
#include <cuda_runtime.h>
#include <cuda_bf16.h>
#include <cstdint>
#include <math.h>

#define Bk 8
#define Ck 64
#define Hk 128
#define Wk 128
#define NPIX (Hk*Wk)                 // 16384
#define PLANE (Ck*NPIX)              // 1,048,576 per batch
#define TENSOR (Bk*PLANE)            // 8,388,608 elements

// ---------------------------------------------------------------------------
// Scratch (device globals; no allocation)
// ---------------------------------------------------------------------------
__device__ float g_tmp_sr[TENSOR];
__device__ float g_tmp_edge[TENSOR];
__device__ float g_kern[Bk * 9 * NPIX];
__device__ float g_fields[Bk * 5 * NPIX];   // sq, dot(0,1), dot(1,-1), dot(1,0), dot(1,1)
// packed bf16 weight fragments:
// [set 4][tap 9][kh 2][kc 2][nc 8][lane 32][term 2][reg 2] u32
__device__ uint32_t g_wpk[4 * 9 * 4096];

// ---------------------------------------------------------------------------
// PTX primitives (base-target: sm_75+/sm_80+)
// ---------------------------------------------------------------------------
#define MMA16816(c, A0, A1, A2, A3, B0, B1)                                  \
    asm volatile(                                                            \
        "mma.sync.aligned.m16n8k16.row.col.f32.bf16.bf16.f32 "               \
        "{%0,%1,%2,%3},{%4,%5,%6,%7},{%8,%9},{%0,%1,%2,%3};"                 \
        : "+f"((c)[0]), "+f"((c)[1]), "+f"((c)[2]), "+f"((c)[3])             \
        : "r"(A0), "r"(A1), "r"(A2), "r"(A3), "r"(B0), "r"(B1))

#define LDMATRIX_X4(r0, r1, r2, r3, addr)                                    \
    asm volatile(                                                            \
        "ldmatrix.sync.aligned.m8n8.x4.shared.b16 {%0,%1,%2,%3}, [%4];"      \
        : "=r"(r0), "=r"(r1), "=r"(r2), "=r"(r3) : "r"(addr))

__device__ __forceinline__ uint32_t smem_u32(const void* p) {
    uint32_t a;
    asm("{ .reg .u64 t; cvta.to.shared.u64 t, %1; cvt.u32.u64 %0, t; }"
        : "=r"(a) : "l"(p));
    return a;
}

// ---------------------------------------------------------------------------
// Weight prep (RN split, done once): [kh][kc][nc][lane][term][reg]
// ---------------------------------------------------------------------------
__global__ void prep_weights(const float* __restrict__ w0,
                             const float* __restrict__ w1,
                             const float* __restrict__ w2,
                             const float* __restrict__ w3) {
    int idx = blockIdx.x * blockDim.x + threadIdx.x;
    if (idx >= 4 * 9 * 4096) return;
    int s    = idx / 36864;
    int rem  = idx % 36864;
    int p    = rem / 4096;
    int rem2 = rem % 4096;
    int kh   = (rem2 >> 11) & 1;
    int kc   = (rem2 >> 10) & 1;
    int nc   = (rem2 >> 7) & 7;
    int l    = (rem2 >> 2) & 31;
    int t    = (rem2 >> 1) & 1;
    int r    = rem2 & 1;

    int o = nc * 8 + (l >> 2);
    int k = kh * 32 + kc * 16 + (l & 3) * 2 + r * 8;

    const float* w = (s == 0) ? w0 : (s == 1) ? w1 : (s == 2) ? w2 : w3;
    float v0 = w[(o * 64 + k) * 9 + p];
    float v1 = w[(o * 64 + k + 1) * 9 + p];

    __nv_bfloat16 h0 = __float2bfloat16_rn(v0);
    __nv_bfloat16 h1 = __float2bfloat16_rn(v1);
    __nv_bfloat16 e0, e1;
    if (t == 0) { e0 = h0; e1 = h1; }
    else {
        e0 = __float2bfloat16_rn(v0 - __bfloat162float(h0));
        e1 = __float2bfloat16_rn(v1 - __bfloat162float(h1));
    }
    uint32_t pk = ((uint32_t)*(uint16_t*)&e1 << 16) | (uint32_t)*(uint16_t*)&e0;
    g_wpk[idx] = pk;
}

// ---------------------------------------------------------------------------
// Pass A: per-pixel fields. sq; dot(0,1); dot(1,e), e=-1,0,1.
// grid (Hk, Bk), 128 thr.
// ---------------------------------------------------------------------------
__global__ void __launch_bounds__(128)
field_kernel(const float* __restrict__ g, float* __restrict__ F) {
    const int h  = blockIdx.x;
    const int bb = blockIdx.y;
    const int w  = threadIdx.x;

    __shared__ float s[8][2][132];

    float sq = 0.f, d01 = 0.f, d1m = 0.f, d10 = 0.f, d1p = 0.f;

    const float* gb = g + bb * PLANE;
    const bool row1ok = (h + 1 < Hk);

    for (int c0 = 0; c0 < 64; c0 += 8) {
        if (c0) __syncthreads();
#pragma unroll
        for (int ch = 0; ch < 8; ch++) {
            const float* gc = gb + (c0 + ch) * NPIX;
            s[ch][0][w + 1] = gc[h * Wk + w];
            s[ch][1][w + 1] = row1ok ? gc[(h + 1) * Wk + w] : 0.f;
            if (w == 0) {
                s[ch][0][0] = 0.f; s[ch][1][0] = 0.f;
                s[ch][0][129] = 0.f; s[ch][1][129] = 0.f;
            }
        }
        __syncthreads();
#pragma unroll
        for (int ch = 0; ch < 8; ch++) {
            float c  = s[ch][0][w + 1];
            float r  = s[ch][0][w + 2];
            float bl = s[ch][1][w];
            float bc = s[ch][1][w + 1];
            float br = s[ch][1][w + 2];
            sq  += c * c;
            d01 += c * r;
            d1m += c * bl;
            d10 += c * bc;
            d1p += c * br;
        }
    }

    float* Fb = F + bb * 5 * NPIX + h * Wk + w;
    Fb[0 * NPIX] = sq;
    Fb[1 * NPIX] = d01;
    Fb[2 * NPIX] = d1m;
    Fb[3 * NPIX] = d10;
    Fb[4 * NPIX] = d1p;
}

// ---------------------------------------------------------------------------
// Pass B: kern[b][p][h][w] = exp(-0.5*(sq_nb + sq_c - 2*dot)).
// ---------------------------------------------------------------------------
__global__ void __launch_bounds__(128)
kern_assemble_kernel(const float* __restrict__ F, float* __restrict__ kout) {
    const int h  = blockIdx.x;
    const int bb = blockIdx.y;
    const int w  = threadIdx.x;

    const float* Fb = F + bb * 5 * NPIX;
    const float sqc = Fb[h * Wk + w];

    float* ko = kout + (bb * 9) * NPIX + h * Wk + w;

#pragma unroll
    for (int p = 0; p < 9; p++) {
        if (p == 4) { ko[4 * NPIX] = 1.0f; continue; }
        const int dy = p / 3 - 1, dx = p % 3 - 1;
        const int row = h + dy, col = w + dx;
        const bool inb = (row >= 0) && (row < Hk) && (col >= 0) && (col < Wk);
        float sqn = 0.f, dot = 0.f;
        if (inb) {
            sqn = Fb[row * Wk + col];
            if (dy == 0) {
                dot = (dx == 1) ? Fb[NPIX + h * Wk + w]
                                : Fb[NPIX + h * Wk + (w - 1)];
            } else if (dy == 1) {
                dot = Fb[(3 + dx) * NPIX + h * Wk + w];
            } else {
                dot = Fb[(3 - dx) * NPIX + (h - 1) * Wk + col];
            }
        }
        float d2 = sqn + sqc - 2.f * dot;
        ko[p * NPIX] = __expf(-0.5f * d2);
    }
}

// ---------------------------------------------------------------------------
// HMMA conv, warp m32n64 tiles, block = 2 image rows (M=256 pix, N=64 cout).
// 256 thr / 8 warps; warp w owns pixels [w*32, w*32+32).
// 18 stages (tap x K-half), double-buffered, 1 barrier/stage.
// A per buf: [hi|lo] 256 rows x 80 B pitch (term stride 20480).
// ---------------------------------------------------------------------------
#define SM_KS   0            // 18*128 f32 = 9216
#define SM_A    9216         // 2 bufs x 40960
#define SM_B    91136        // 2 bufs x 8192
#define CONV_SMEM 107520

__global__ void __launch_bounds__(256, 2)
conv3x3_hmma_kernel(const float* __restrict__ x0,
                    const float* __restrict__ kern0,   // null => plain
                    const uint32_t* __restrict__ wt0,
                    const float* __restrict__ bias0,
                    const float* __restrict__ resid0,
                    float* __restrict__ out0,
                    const float* __restrict__ x1,
                    const uint32_t* __restrict__ wt1,
                    const float* __restrict__ bias1,
                    const float* __restrict__ resid1,
                    float* __restrict__ out1,
                    int do_relu) {
    extern __shared__ char smem[];
    float* k_s = (float*)(smem + SM_KS);
    const uint32_t sb = smem_u32(smem);

    const int h0 = blockIdx.x * 2;
    const int bb = blockIdx.y;
    const int z  = blockIdx.z;

    const float*    x     = z ? x1 : x0;
    const float*    kern  = z ? nullptr : kern0;
    const uint32_t* wt    = z ? wt1 : wt0;
    const float*    bias  = z ? bias1 : bias0;
    const float*    resid = z ? resid1 : resid0;
    float*          out   = z ? out1 : out0;

    const int tid  = threadIdx.x;
    const int warp = tid >> 5;
    const int lane = tid & 31;
    const int gq   = lane >> 2;
    const int tq   = lane & 3;

    // stage kern rows: k_s[p][r][c], idx = p*256 + r*128 + c
    for (int i = tid; i < 18 * 128; i += 256) {
        int p = i >> 8, r = (i >> 7) & 1, c = i & 127;
        k_s[i] = kern ? kern[((bb * 9 + p) * Hk + h0 + r) * Wk + c] : 1.0f;
    }
    __syncthreads();

    float acc[2][8][4];
#pragma unroll
    for (int hf = 0; hf < 2; hf++)
#pragma unroll
        for (int n = 0; n < 8; n++)
#pragma unroll
            for (int i = 0; i < 4; i++) acc[hf][n][i] = 0.f;

    const float* xb = x + bb * PLANE;

    // A staging: thread -> pixel q = tid (0..255), all 32 channels of K-half
    const int sr = tid >> 7;            // tile row 0/1
    const int sc = tid & 127;           // col

#define STAGE(S, BUF) do {                                                    \
    const int p_  = (S) >> 1;                                                 \
    const int kh_ = ((S) & 1) << 5;                                           \
    /* B: 8 KB contiguous copy */                                             \
    {                                                                         \
        const uint4* src = (const uint4*)(wt + p_ * 4096 + (((S) & 1) << 11));\
        uint4* dst = (uint4*)(smem + SM_B + (BUF) * 8192);                    \
        dst[tid] = src[tid];                                                  \
        dst[tid + 256] = src[tid + 256];                                      \
    }                                                                         \
    /* A: pixel tid, 32 channels, kern folded, trunc hi / residual lo */      \
    {                                                                         \
        const int dy = p_ / 3 - 1, dx = p_ % 3 - 1;                           \
        const int row = h0 + sr + dy, col = sc + dx;                          \
        const bool ok = (row >= 0) && (row < Hk) && (col >= 0) && (col < Wk); \
        const float kv = k_s[p_ * 256 + sr * 128 + sc];                       \
        const float* src = xb + (size_t)kh_ * NPIX + row * Wk + col;          \
        char* ah = smem + SM_A + (BUF) * 40960 + tid * 80;                    \
        char* al = ah + 20480;                                                \
        _Pragma("unroll")                                                     \
        for (int i = 0; i < 32; i += 2) {                                     \
            float v0 = 0.f, v1 = 0.f;                                         \
            if (ok) {                                                         \
                v0 = src[(size_t)i * NPIX] * kv;                              \
                v1 = src[(size_t)(i + 1) * NPIX] * kv;                        \
            }                                                                 \
            uint32_t u0 = __float_as_uint(v0);                                \
            uint32_t u1 = __float_as_uint(v1);                                \
            uint32_t hipk = __byte_perm(u0, u1, 0x7632);                      \
            float lo0 = v0 - __uint_as_float(u0 & 0xffff0000u);               \
            float lo1 = v1 - __uint_as_float(u1 & 0xffff0000u);               \
            float2 lf; lf.x = lo0; lf.y = lo1;                                \
            __nv_bfloat162 lp = __float22bfloat162_rn(lf);                    \
            *(uint32_t*)(ah + i * 2) = hipk;                                  \
            *(__nv_bfloat162*)(al + i * 2) = lp;                              \
        }                                                                     \
    }                                                                         \
} while (0)

    // prologue
    STAGE(0, 0);

    // ldmatrix lane address: rows warp*32 + (lane&15) (+16 for half 1)
    const uint32_t lmoff =
        (uint32_t)((warp * 32 + (lane & 15)) * 80 + ((lane >> 4) << 4));

    for (int s = 0; s < 18; s++) {
        const int cur = s & 1;
        __syncthreads();
        if (s + 1 < 18) STAGE(s + 1, cur ^ 1);

        const uint32_t aA = sb + SM_A + cur * 40960 + lmoff;
        const uint4* b4 = (const uint4*)(smem + SM_B + cur * 8192);
#pragma unroll
        for (int kc = 0; kc < 2; kc++) {
            uint32_t a0h[4], a1h[4], a0l[4], a1l[4];
            LDMATRIX_X4(a0h[0], a0h[1], a0h[2], a0h[3], aA + kc * 32);
            LDMATRIX_X4(a1h[0], a1h[1], a1h[2], a1h[3], aA + kc * 32 + 1280);
            LDMATRIX_X4(a0l[0], a0l[1], a0l[2], a0l[3], aA + kc * 32 + 20480);
            LDMATRIX_X4(a1l[0], a1l[1], a1l[2], a1l[3], aA + kc * 32 + 21760);
#pragma unroll
            for (int nc = 0; nc < 8; nc++) {
                uint4 bv = b4[(kc * 8 + nc) * 32 + lane];
                MMA16816(acc[0][nc], a0h[0], a0h[1], a0h[2], a0h[3], bv.x, bv.y);
                MMA16816(acc[0][nc], a0h[0], a0h[1], a0h[2], a0h[3], bv.z, bv.w);
                MMA16816(acc[0][nc], a0l[0], a0l[1], a0l[2], a0l[3], bv.x, bv.y);
                MMA16816(acc[1][nc], a1h[0], a1h[1], a1h[2], a1h[3], bv.x, bv.y);
                MMA16816(acc[1][nc], a1h[0], a1h[1], a1h[2], a1h[3], bv.z, bv.w);
                MMA16816(acc[1][nc], a1l[0], a1l[1], a1l[2], a1l[3], bv.x, bv.y);
            }
        }
    }

    // epilogue: half hf -> pixel q = warp*32 + hf*16 + gq (and q+8)
#pragma unroll
    for (int hf = 0; hf < 2; hf++) {
        const int q = warp * 32 + hf * 16 + gq;
        const int r = q >> 7, cpix = q & 127;
        const int rowoff = (h0 + r) * Wk + cpix;
#pragma unroll
        for (int nc = 0; nc < 8; nc++) {
            int o0 = nc * 8 + tq * 2;
            float bv0 = __ldg(bias + o0);
            float bv1 = __ldg(bias + o0 + 1);
            float v00 = acc[hf][nc][0] + bv0;
            float v01 = acc[hf][nc][1] + bv1;
            float v10 = acc[hf][nc][2] + bv0;
            float v11 = acc[hf][nc][3] + bv1;
            if (do_relu) {
                v00 = fmaxf(v00, 0.f); v01 = fmaxf(v01, 0.f);
                v10 = fmaxf(v10, 0.f); v11 = fmaxf(v11, 0.f);
            }
            int i00 = (bb * Ck + o0) * NPIX + rowoff;
            if (resid) {
                v00 += resid[i00];
                v01 += resid[i00 + NPIX];
                v10 += resid[i00 + 8];
                v11 += resid[i00 + NPIX + 8];
            }
            out[i00] = v00;
            out[i00 + NPIX] = v01;
            out[i00 + 8] = v10;
            out[i00 + NPIX + 8] = v11;
        }
    }
}

// ---------------------------------------------------------------------------
extern "C" void kernel_launch(void* const* d_in, const int* in_sizes, int n_in,
                              void* d_out, int out_size) {
    const float* x      = (const float*)d_in[0];
    const float* edge   = (const float*)d_in[1];
    const float* w_pac1 = (const float*)d_in[2];
    const float* b_pac1 = (const float*)d_in[3];
    const float* w_pac2 = (const float*)d_in[4];
    const float* b_pac2 = (const float*)d_in[5];
    const float* w_e1   = (const float*)d_in[6];
    const float* b_e1   = (const float*)d_in[7];
    const float* w_e2   = (const float*)d_in[8];
    const float* b_e2   = (const float*)d_in[9];

    float* out_sr   = (float*)d_out;
    float* out_edge = out_sr + TENSOR;

    float *p_tmp_sr, *p_tmp_edge, *p_kern, *p_fields;
    uint32_t* p_wpk;
    cudaGetSymbolAddress((void**)&p_tmp_sr, g_tmp_sr);
    cudaGetSymbolAddress((void**)&p_tmp_edge, g_tmp_edge);
    cudaGetSymbolAddress((void**)&p_kern, g_kern);
    cudaGetSymbolAddress((void**)&p_fields, g_fields);
    cudaGetSymbolAddress((void**)&p_wpk, g_wpk);

    cudaFuncSetAttribute(conv3x3_hmma_kernel,
                         cudaFuncAttributeMaxDynamicSharedMemorySize, CONV_SMEM);

    prep_weights<<<(4 * 9 * 4096 + 255) / 256, 256>>>(w_pac1, w_pac2, w_e1, w_e2);

    dim3 kgrid(Hk, Bk);
    dim3 cgrid(Hk / 2, Bk, 2);
    const int WS = 9 * 4096;

    // stage 1: kern(edge); z=0 pac(x), z=1 plain conv(edge); both relu
    field_kernel<<<kgrid, 128>>>(edge, p_fields);
    kern_assemble_kernel<<<kgrid, 128>>>(p_fields, p_kern);
    conv3x3_hmma_kernel<<<cgrid, 256, CONV_SMEM>>>(
        x,    p_kern, p_wpk + 0 * WS, b_pac1, nullptr, p_tmp_sr,
        edge,         p_wpk + 2 * WS, b_e1,   nullptr, p_tmp_edge, 1);

    // stage 2: kern(tmp_edge); z=0 pac(tmp_sr)+x, z=1 conv(tmp_edge)+edge
    field_kernel<<<kgrid, 128>>>(p_tmp_edge, p_fields);
    kern_assemble_kernel<<<kgrid, 128>>>(p_fields, p_kern);
    conv3x3_hmma_kernel<<<cgrid, 256, CONV_SMEM>>>(
        p_tmp_sr,   p_kern, p_wpk + 1 * WS, b_pac2, x,    out_sr,
        p_tmp_edge,         p_wpk + 3 * WS, b_e2,   edge, out_edge, 0);
}

// round 9
// speedup vs baseline: 2.7643x; 1.1833x over previous
#include <cuda_runtime.h>
#include <cuda_fp16.h>
#include <cstdint>
#include <math.h>

#define Bk 8
#define Ck 64
#define Hk 128
#define Wk 128
#define NPIX (Hk*Wk)                 // 16384
#define PLANE (Ck*NPIX)              // 1,048,576 per batch
#define TENSOR (Bk*PLANE)            // 8,388,608 elements

// ---------------------------------------------------------------------------
// Scratch (device globals; no allocation)
// ---------------------------------------------------------------------------
__device__ float g_tmp_sr[TENSOR];
__device__ float g_tmp_edge[TENSOR];
__device__ float g_kern[Bk * 9 * NPIX];
__device__ float g_fields[Bk * 5 * NPIX];   // sq, dot(0,1), dot(1,-1), dot(1,0), dot(1,1)
// packed fp16 weight fragments (single term):
// [set 4][tap 9][kh 2][kc 2][nc 8][lane 32][reg 2] u32
__device__ uint32_t g_wpk[4 * 9 * 2048];

// ---------------------------------------------------------------------------
// PTX primitives (base-target: sm_75+/sm_80+)
// ---------------------------------------------------------------------------
#define MMAF16(c, A0, A1, A2, A3, B0, B1)                                    \
    asm volatile(                                                            \
        "mma.sync.aligned.m16n8k16.row.col.f32.f16.f16.f32 "                 \
        "{%0,%1,%2,%3},{%4,%5,%6,%7},{%8,%9},{%0,%1,%2,%3};"                 \
        : "+f"((c)[0]), "+f"((c)[1]), "+f"((c)[2]), "+f"((c)[3])             \
        : "r"(A0), "r"(A1), "r"(A2), "r"(A3), "r"(B0), "r"(B1))

#define LDMATRIX_X4(r0, r1, r2, r3, addr)                                    \
    asm volatile(                                                            \
        "ldmatrix.sync.aligned.m8n8.x4.shared.b16 {%0,%1,%2,%3}, [%4];"      \
        : "=r"(r0), "=r"(r1), "=r"(r2), "=r"(r3) : "r"(addr))

__device__ __forceinline__ uint32_t smem_u32(const void* p) {
    uint32_t a;
    asm("{ .reg .u64 t; cvta.to.shared.u64 t, %1; cvt.u32.u64 %0, t; }"
        : "=r"(a) : "l"(p));
    return a;
}

// ---------------------------------------------------------------------------
// Weight prep (single fp16 term): [kh][kc][nc][lane][reg]
// ---------------------------------------------------------------------------
__global__ void prep_weights(const float* __restrict__ w0,
                             const float* __restrict__ w1,
                             const float* __restrict__ w2,
                             const float* __restrict__ w3) {
    int idx = blockIdx.x * blockDim.x + threadIdx.x;
    if (idx >= 4 * 9 * 2048) return;
    int s    = idx / 18432;
    int rem  = idx % 18432;
    int p    = rem / 2048;
    int rem2 = rem % 2048;
    int kh   = (rem2 >> 10) & 1;
    int kc   = (rem2 >> 9) & 1;
    int nc   = (rem2 >> 6) & 7;
    int l    = (rem2 >> 1) & 31;
    int r    = rem2 & 1;

    int o = nc * 8 + (l >> 2);
    int k = kh * 32 + kc * 16 + (l & 3) * 2 + r * 8;

    const float* w = (s == 0) ? w0 : (s == 1) ? w1 : (s == 2) ? w2 : w3;
    float2 v;
    v.x = w[(o * 64 + k) * 9 + p];
    v.y = w[(o * 64 + k + 1) * 9 + p];
    __half2 h2 = __float22half2_rn(v);
    g_wpk[idx] = *(uint32_t*)&h2;
}

// ---------------------------------------------------------------------------
// Pass A: per-pixel fields. sq; dot(0,1); dot(1,e), e=-1,0,1.
// grid (Hk, Bk), 128 thr.
// ---------------------------------------------------------------------------
__global__ void __launch_bounds__(128)
field_kernel(const float* __restrict__ g, float* __restrict__ F) {
    const int h  = blockIdx.x;
    const int bb = blockIdx.y;
    const int w  = threadIdx.x;

    __shared__ float s[8][2][132];

    float sq = 0.f, d01 = 0.f, d1m = 0.f, d10 = 0.f, d1p = 0.f;

    const float* gb = g + bb * PLANE;
    const bool row1ok = (h + 1 < Hk);

    for (int c0 = 0; c0 < 64; c0 += 8) {
        if (c0) __syncthreads();
#pragma unroll
        for (int ch = 0; ch < 8; ch++) {
            const float* gc = gb + (c0 + ch) * NPIX;
            s[ch][0][w + 1] = gc[h * Wk + w];
            s[ch][1][w + 1] = row1ok ? gc[(h + 1) * Wk + w] : 0.f;
            if (w == 0) {
                s[ch][0][0] = 0.f; s[ch][1][0] = 0.f;
                s[ch][0][129] = 0.f; s[ch][1][129] = 0.f;
            }
        }
        __syncthreads();
#pragma unroll
        for (int ch = 0; ch < 8; ch++) {
            float c  = s[ch][0][w + 1];
            float r  = s[ch][0][w + 2];
            float bl = s[ch][1][w];
            float bc = s[ch][1][w + 1];
            float br = s[ch][1][w + 2];
            sq  += c * c;
            d01 += c * r;
            d1m += c * bl;
            d10 += c * bc;
            d1p += c * br;
        }
    }

    float* Fb = F + bb * 5 * NPIX + h * Wk + w;
    Fb[0 * NPIX] = sq;
    Fb[1 * NPIX] = d01;
    Fb[2 * NPIX] = d1m;
    Fb[3 * NPIX] = d10;
    Fb[4 * NPIX] = d1p;
}

// ---------------------------------------------------------------------------
// Pass B: kern[b][p][h][w] = exp(-0.5*(sq_nb + sq_c - 2*dot)).
// ---------------------------------------------------------------------------
__global__ void __launch_bounds__(128)
kern_assemble_kernel(const float* __restrict__ F, float* __restrict__ kout) {
    const int h  = blockIdx.x;
    const int bb = blockIdx.y;
    const int w  = threadIdx.x;

    const float* Fb = F + bb * 5 * NPIX;
    const float sqc = Fb[h * Wk + w];

    float* ko = kout + (bb * 9) * NPIX + h * Wk + w;

#pragma unroll
    for (int p = 0; p < 9; p++) {
        if (p == 4) { ko[4 * NPIX] = 1.0f; continue; }
        const int dy = p / 3 - 1, dx = p % 3 - 1;
        const int row = h + dy, col = w + dx;
        const bool inb = (row >= 0) && (row < Hk) && (col >= 0) && (col < Wk);
        float sqn = 0.f, dot = 0.f;
        if (inb) {
            sqn = Fb[row * Wk + col];
            if (dy == 0) {
                dot = (dx == 1) ? Fb[NPIX + h * Wk + w]
                                : Fb[NPIX + h * Wk + (w - 1)];
            } else if (dy == 1) {
                dot = Fb[(3 + dx) * NPIX + h * Wk + w];
            } else {
                dot = Fb[(3 - dx) * NPIX + (h - 1) * Wk + col];
            }
        }
        float d2 = sqn + sqc - 2.f * dot;
        ko[p * NPIX] = __expf(-0.5f * d2);
    }
}

// ---------------------------------------------------------------------------
// HMMA conv (fp16 2-term x-split, single-term w).
// Block = 2 image rows (M=256 pix, N=64 cout), 256 thr / 8 warps.
// Warp w: pixels [w*32, w*32+32). 18 stages (tap x K-half), double-buffered.
// A per buf: [hi|lo] 256 rows x 80 B pitch (term stride 20480).
// ---------------------------------------------------------------------------
#define SM_KS   0            // 18*128 f32 = 9216
#define SM_A    9216         // 2 bufs x 40960
#define SM_B    91136        // 2 bufs x 4096
#define CONV_SMEM 99328

__global__ void __launch_bounds__(256, 2)
conv3x3_hmma_kernel(const float* __restrict__ x0,
                    const float* __restrict__ kern0,   // null => plain
                    const uint32_t* __restrict__ wt0,
                    const float* __restrict__ bias0,
                    const float* __restrict__ resid0,
                    float* __restrict__ out0,
                    const float* __restrict__ x1,
                    const uint32_t* __restrict__ wt1,
                    const float* __restrict__ bias1,
                    const float* __restrict__ resid1,
                    float* __restrict__ out1,
                    int do_relu) {
    extern __shared__ char smem[];
    float* k_s = (float*)(smem + SM_KS);
    const uint32_t sb = smem_u32(smem);

    const int h0 = blockIdx.x * 2;
    const int bb = blockIdx.y;
    const int z  = blockIdx.z;

    const float*    x     = z ? x1 : x0;
    const float*    kern  = z ? nullptr : kern0;
    const uint32_t* wt    = z ? wt1 : wt0;
    const float*    bias  = z ? bias1 : bias0;
    const float*    resid = z ? resid1 : resid0;
    float*          out   = z ? out1 : out0;

    const int tid  = threadIdx.x;
    const int warp = tid >> 5;
    const int lane = tid & 31;
    const int gq   = lane >> 2;
    const int tq   = lane & 3;

    // stage kern rows: k_s[p][r][c]
    for (int i = tid; i < 18 * 128; i += 256) {
        int p = i >> 8, r = (i >> 7) & 1, c = i & 127;
        k_s[i] = kern ? kern[((bb * 9 + p) * Hk + h0 + r) * Wk + c] : 1.0f;
    }
    __syncthreads();

    float acc[2][8][4];
#pragma unroll
    for (int hf = 0; hf < 2; hf++)
#pragma unroll
        for (int n = 0; n < 8; n++)
#pragma unroll
            for (int i = 0; i < 4; i++) acc[hf][n][i] = 0.f;

    const float* xb = x + bb * PLANE;

    const int sr = tid >> 7;            // tile row 0/1
    const int sc = tid & 127;           // col

#define STAGE(S, BUF) do {                                                    \
    const int p_  = (S) >> 1;                                                 \
    const int kh_ = ((S) & 1) << 5;                                           \
    /* B: 4 KB contiguous copy */                                             \
    {                                                                         \
        const uint4* src = (const uint4*)(wt + p_ * 2048 + (((S) & 1) << 10));\
        uint4* dst = (uint4*)(smem + SM_B + (BUF) * 4096);                    \
        dst[tid] = src[tid];                                                  \
    }                                                                         \
    /* A: pixel tid, 32 channels, kern folded, fp16 hi + exact residual lo */ \
    {                                                                         \
        const int dy = p_ / 3 - 1, dx = p_ % 3 - 1;                           \
        const int row = h0 + sr + dy, col = sc + dx;                          \
        const bool ok = (row >= 0) && (row < Hk) && (col >= 0) && (col < Wk); \
        const float kv = k_s[p_ * 256 + sr * 128 + sc];                       \
        const float* src = xb + (size_t)kh_ * NPIX + row * Wk + col;          \
        char* ah = smem + SM_A + (BUF) * 40960 + tid * 80;                    \
        char* al = ah + 20480;                                                \
        _Pragma("unroll")                                                     \
        for (int i = 0; i < 32; i += 2) {                                     \
            float2 v; v.x = 0.f; v.y = 0.f;                                   \
            if (ok) {                                                         \
                v.x = src[(size_t)i * NPIX] * kv;                             \
                v.y = src[(size_t)(i + 1) * NPIX] * kv;                       \
            }                                                                 \
            __half2 hp = __float22half2_rn(v);                                \
            float2 hb = __half22float2(hp);                                   \
            float2 lf; lf.x = v.x - hb.x; lf.y = v.y - hb.y;                  \
            __half2 lp = __float22half2_rn(lf);                               \
            *(__half2*)(ah + i * 2) = hp;                                     \
            *(__half2*)(al + i * 2) = lp;                                     \
        }                                                                     \
    }                                                                         \
} while (0)

    // prologue
    STAGE(0, 0);

    const uint32_t lmoff =
        (uint32_t)((warp * 32 + (lane & 15)) * 80 + ((lane >> 4) << 4));

    for (int s = 0; s < 18; s++) {
        const int cur = s & 1;
        __syncthreads();
        if (s + 1 < 18) STAGE(s + 1, cur ^ 1);

        const uint32_t aA = sb + SM_A + cur * 40960 + lmoff;
        const uint2* b2 = (const uint2*)(smem + SM_B + cur * 4096);
#pragma unroll
        for (int kc = 0; kc < 2; kc++) {
            uint32_t a0h[4], a1h[4], a0l[4], a1l[4];
            LDMATRIX_X4(a0h[0], a0h[1], a0h[2], a0h[3], aA + kc * 32);
            LDMATRIX_X4(a1h[0], a1h[1], a1h[2], a1h[3], aA + kc * 32 + 1280);
            LDMATRIX_X4(a0l[0], a0l[1], a0l[2], a0l[3], aA + kc * 32 + 20480);
            LDMATRIX_X4(a1l[0], a1l[1], a1l[2], a1l[3], aA + kc * 32 + 21760);
#pragma unroll
            for (int nc = 0; nc < 8; nc++) {
                uint2 bv = b2[(kc * 8 + nc) * 32 + lane];
                MMAF16(acc[0][nc], a0h[0], a0h[1], a0h[2], a0h[3], bv.x, bv.y);
                MMAF16(acc[0][nc], a0l[0], a0l[1], a0l[2], a0l[3], bv.x, bv.y);
                MMAF16(acc[1][nc], a1h[0], a1h[1], a1h[2], a1h[3], bv.x, bv.y);
                MMAF16(acc[1][nc], a1l[0], a1l[1], a1l[2], a1l[3], bv.x, bv.y);
            }
        }
    }

    // epilogue: half hf -> pixel q = warp*32 + hf*16 + gq (and q+8)
#pragma unroll
    for (int hf = 0; hf < 2; hf++) {
        const int q = warp * 32 + hf * 16 + gq;
        const int r = q >> 7, cpix = q & 127;
        const int rowoff = (h0 + r) * Wk + cpix;
#pragma unroll
        for (int nc = 0; nc < 8; nc++) {
            int o0 = nc * 8 + tq * 2;
            float bv0 = __ldg(bias + o0);
            float bv1 = __ldg(bias + o0 + 1);
            float v00 = acc[hf][nc][0] + bv0;
            float v01 = acc[hf][nc][1] + bv1;
            float v10 = acc[hf][nc][2] + bv0;
            float v11 = acc[hf][nc][3] + bv1;
            if (do_relu) {
                v00 = fmaxf(v00, 0.f); v01 = fmaxf(v01, 0.f);
                v10 = fmaxf(v10, 0.f); v11 = fmaxf(v11, 0.f);
            }
            int i00 = (bb * Ck + o0) * NPIX + rowoff;
            if (resid) {
                v00 += resid[i00];
                v01 += resid[i00 + NPIX];
                v10 += resid[i00 + 8];
                v11 += resid[i00 + NPIX + 8];
            }
            out[i00] = v00;
            out[i00 + NPIX] = v01;
            out[i00 + 8] = v10;
            out[i00 + NPIX + 8] = v11;
        }
    }
}

// ---------------------------------------------------------------------------
extern "C" void kernel_launch(void* const* d_in, const int* in_sizes, int n_in,
                              void* d_out, int out_size) {
    const float* x      = (const float*)d_in[0];
    const float* edge   = (const float*)d_in[1];
    const float* w_pac1 = (const float*)d_in[2];
    const float* b_pac1 = (const float*)d_in[3];
    const float* w_pac2 = (const float*)d_in[4];
    const float* b_pac2 = (const float*)d_in[5];
    const float* w_e1   = (const float*)d_in[6];
    const float* b_e1   = (const float*)d_in[7];
    const float* w_e2   = (const float*)d_in[8];
    const float* b_e2   = (const float*)d_in[9];

    float* out_sr   = (float*)d_out;
    float* out_edge = out_sr + TENSOR;

    float *p_tmp_sr, *p_tmp_edge, *p_kern, *p_fields;
    uint32_t* p_wpk;
    cudaGetSymbolAddress((void**)&p_tmp_sr, g_tmp_sr);
    cudaGetSymbolAddress((void**)&p_tmp_edge, g_tmp_edge);
    cudaGetSymbolAddress((void**)&p_kern, g_kern);
    cudaGetSymbolAddress((void**)&p_fields, g_fields);
    cudaGetSymbolAddress((void**)&p_wpk, g_wpk);

    cudaFuncSetAttribute(conv3x3_hmma_kernel,
                         cudaFuncAttributeMaxDynamicSharedMemorySize, CONV_SMEM);

    prep_weights<<<(4 * 9 * 2048 + 255) / 256, 256>>>(w_pac1, w_pac2, w_e1, w_e2);

    dim3 kgrid(Hk, Bk);
    dim3 cgrid(Hk / 2, Bk, 2);
    const int WS = 9 * 2048;

    // stage 1: kern(edge); z=0 pac(x), z=1 plain conv(edge); both relu
    field_kernel<<<kgrid, 128>>>(edge, p_fields);
    kern_assemble_kernel<<<kgrid, 128>>>(p_fields, p_kern);
    conv3x3_hmma_kernel<<<cgrid, 256, CONV_SMEM>>>(
        x,    p_kern, p_wpk + 0 * WS, b_pac1, nullptr, p_tmp_sr,
        edge,         p_wpk + 2 * WS, b_e1,   nullptr, p_tmp_edge, 1);

    // stage 2: kern(tmp_edge); z=0 pac(tmp_sr)+x, z=1 conv(tmp_edge)+edge
    field_kernel<<<kgrid, 128>>>(p_tmp_edge, p_fields);
    kern_assemble_kernel<<<kgrid, 128>>>(p_fields, p_kern);
    conv3x3_hmma_kernel<<<cgrid, 256, CONV_SMEM>>>(
        p_tmp_sr,   p_kern, p_wpk + 1 * WS, b_pac2, x,    out_sr,
        p_tmp_edge,         p_wpk + 3 * WS, b_e2,   edge, out_edge, 0);
}

// round 10
// speedup vs baseline: 3.6788x; 1.3308x over previous
#include <cuda_runtime.h>
#include <cuda_fp16.h>
#include <cstdint>
#include <math.h>

#define Bk 8
#define Ck 64
#define Hk 128
#define Wk 128
#define NPIX (Hk*Wk)                 // 16384
#define PLANE (Ck*NPIX)              // 1,048,576 per batch
#define TENSOR (Bk*PLANE)            // 8,388,608 elements

// ---------------------------------------------------------------------------
// Scratch (device globals; no allocation)
// ---------------------------------------------------------------------------
__device__ float g_tmp_sr[TENSOR];
__device__ float g_tmp_edge[TENSOR];
__device__ float g_kern[Bk * 9 * NPIX];
__device__ float g_fields[Bk * 5 * NPIX];   // sq, dot(0,1), dot(1,-1), dot(1,0), dot(1,1)
// packed fp16 weight fragments (single term):
// [set 4][tap 9][kh 2][kc 2][nc 8][lane 32][reg 2] u32
__device__ uint32_t g_wpk[4 * 9 * 2048];

// ---------------------------------------------------------------------------
// PTX primitives
// ---------------------------------------------------------------------------
#define MMAF16(c, A0, A1, A2, A3, B0, B1)                                    \
    asm volatile(                                                            \
        "mma.sync.aligned.m16n8k16.row.col.f32.f16.f16.f32 "                 \
        "{%0,%1,%2,%3},{%4,%5,%6,%7},{%8,%9},{%0,%1,%2,%3};"                 \
        : "+f"((c)[0]), "+f"((c)[1]), "+f"((c)[2]), "+f"((c)[3])             \
        : "r"(A0), "r"(A1), "r"(A2), "r"(A3), "r"(B0), "r"(B1))

// ---------------------------------------------------------------------------
// Weight prep (single fp16 term): [kh][kc][nc][lane][reg]
// B fragment (col-major): reg r of lane l = {w[o][k], w[o][k+1]},
// o = nc*8 + (l>>2), k = kh*32 + kc*16 + (l&3)*2 + r*8.
// ---------------------------------------------------------------------------
__global__ void prep_weights(const float* __restrict__ w0,
                             const float* __restrict__ w1,
                             const float* __restrict__ w2,
                             const float* __restrict__ w3) {
    int idx = blockIdx.x * blockDim.x + threadIdx.x;
    if (idx >= 4 * 9 * 2048) return;
    int s    = idx / 18432;
    int rem  = idx % 18432;
    int p    = rem / 2048;
    int rem2 = rem % 2048;
    int kh   = (rem2 >> 10) & 1;
    int kc   = (rem2 >> 9) & 1;
    int nc   = (rem2 >> 6) & 7;
    int l    = (rem2 >> 1) & 31;
    int r    = rem2 & 1;

    int o = nc * 8 + (l >> 2);
    int k = kh * 32 + kc * 16 + (l & 3) * 2 + r * 8;

    const float* w = (s == 0) ? w0 : (s == 1) ? w1 : (s == 2) ? w2 : w3;
    float2 v;
    v.x = w[(o * 64 + k) * 9 + p];
    v.y = w[(o * 64 + k + 1) * 9 + p];
    __half2 h2 = __float22half2_rn(v);
    g_wpk[idx] = *(uint32_t*)&h2;
}

// ---------------------------------------------------------------------------
// Pass A: per-pixel fields. sq; dot(0,1); dot(1,e), e=-1,0,1.
// ---------------------------------------------------------------------------
__global__ void __launch_bounds__(128)
field_kernel(const float* __restrict__ g, float* __restrict__ F) {
    const int h  = blockIdx.x;
    const int bb = blockIdx.y;
    const int w  = threadIdx.x;

    __shared__ float s[8][2][132];

    float sq = 0.f, d01 = 0.f, d1m = 0.f, d10 = 0.f, d1p = 0.f;

    const float* gb = g + bb * PLANE;
    const bool row1ok = (h + 1 < Hk);

    for (int c0 = 0; c0 < 64; c0 += 8) {
        if (c0) __syncthreads();
#pragma unroll
        for (int ch = 0; ch < 8; ch++) {
            const float* gc = gb + (c0 + ch) * NPIX;
            s[ch][0][w + 1] = gc[h * Wk + w];
            s[ch][1][w + 1] = row1ok ? gc[(h + 1) * Wk + w] : 0.f;
            if (w == 0) {
                s[ch][0][0] = 0.f; s[ch][1][0] = 0.f;
                s[ch][0][129] = 0.f; s[ch][1][129] = 0.f;
            }
        }
        __syncthreads();
#pragma unroll
        for (int ch = 0; ch < 8; ch++) {
            float c  = s[ch][0][w + 1];
            float r  = s[ch][0][w + 2];
            float bl = s[ch][1][w];
            float bc = s[ch][1][w + 1];
            float br = s[ch][1][w + 2];
            sq  += c * c;
            d01 += c * r;
            d1m += c * bl;
            d10 += c * bc;
            d1p += c * br;
        }
    }

    float* Fb = F + bb * 5 * NPIX + h * Wk + w;
    Fb[0 * NPIX] = sq;
    Fb[1 * NPIX] = d01;
    Fb[2 * NPIX] = d1m;
    Fb[3 * NPIX] = d10;
    Fb[4 * NPIX] = d1p;
}

// ---------------------------------------------------------------------------
// Pass B: kern[b][p][h][w] = exp(-0.5*(sq_nb + sq_c - 2*dot)).
// ---------------------------------------------------------------------------
__global__ void __launch_bounds__(128)
kern_assemble_kernel(const float* __restrict__ F, float* __restrict__ kout) {
    const int h  = blockIdx.x;
    const int bb = blockIdx.y;
    const int w  = threadIdx.x;

    const float* Fb = F + bb * 5 * NPIX;
    const float sqc = Fb[h * Wk + w];

    float* ko = kout + (bb * 9) * NPIX + h * Wk + w;

#pragma unroll
    for (int p = 0; p < 9; p++) {
        if (p == 4) { ko[4 * NPIX] = 1.0f; continue; }
        const int dy = p / 3 - 1, dx = p % 3 - 1;
        const int row = h + dy, col = w + dx;
        const bool inb = (row >= 0) && (row < Hk) && (col >= 0) && (col < Wk);
        float sqn = 0.f, dot = 0.f;
        if (inb) {
            sqn = Fb[row * Wk + col];
            if (dy == 0) {
                dot = (dx == 1) ? Fb[NPIX + h * Wk + w]
                                : Fb[NPIX + h * Wk + (w - 1)];
            } else if (dy == 1) {
                dot = Fb[(3 + dx) * NPIX + h * Wk + w];
            } else {
                dot = Fb[(3 - dx) * NPIX + (h - 1) * Wk + col];
            }
        }
        float d2 = sqn + sqc - 2.f * dot;
        ko[p * NPIX] = __expf(-0.5f * d2);
    }
}

// ---------------------------------------------------------------------------
// HMMA conv, register-direct A and B fragments (NO shared memory, NO barriers).
// Block = 2 image rows (M=256 pix, N=64 cout), 256 thr / 8 warps.
// Warp w: output row h0 + (w>>2), cols [(w&3)*32, +32). fp16 2-term x-split.
// ---------------------------------------------------------------------------
__global__ void __launch_bounds__(256, 2)
conv3x3_hmma_kernel(const float* __restrict__ x0,
                    const float* __restrict__ kern0,   // null => plain
                    const uint32_t* __restrict__ wt0,
                    const float* __restrict__ bias0,
                    const float* __restrict__ resid0,
                    float* __restrict__ out0,
                    const float* __restrict__ x1,
                    const uint32_t* __restrict__ wt1,
                    const float* __restrict__ bias1,
                    const float* __restrict__ resid1,
                    float* __restrict__ out1,
                    int do_relu) {
    const int h0 = blockIdx.x * 2;
    const int bb = blockIdx.y;
    const int z  = blockIdx.z;

    const float*    x     = z ? x1 : x0;
    const float*    kern  = z ? nullptr : kern0;
    const uint32_t* wt    = z ? wt1 : wt0;
    const float*    bias  = z ? bias1 : bias0;
    const float*    resid = z ? resid1 : resid0;
    float*          out   = z ? out1 : out0;

    const int tid  = threadIdx.x;
    const int warp = tid >> 5;
    const int lane = tid & 31;
    const int gq   = lane >> 2;
    const int tq   = lane & 3;
    const int wr   = warp >> 2;            // warp output row 0/1
    const int c0   = (warp & 3) << 5;      // col base
    const int row_out = h0 + wr;

    // lane pixels: [mh][rr] = c0 + mh*16 + gq + rr*8
    int pixc[2][2];
    pixc[0][0] = c0 + gq;      pixc[0][1] = c0 + gq + 8;
    pixc[1][0] = c0 + 16 + gq; pixc[1][1] = c0 + 24 + gq;

    float acc[2][8][4];
#pragma unroll
    for (int mh = 0; mh < 2; mh++)
#pragma unroll
        for (int n = 0; n < 8; n++)
#pragma unroll
            for (int i = 0; i < 4; i++) acc[mh][n][i] = 0.f;

    const float* xb = x + bb * PLANE;

    for (int p = 0; p < 9; p++) {
        const int dy = p / 3 - 1, dx = p % 3 - 1;
        const int row = row_out + dy;
        if (row < 0 || row >= Hk) continue;   // zero contribution, skip

        // kern values at OUTPUT pixels (row_out, pixc)
        float kv[2][2];
        if (kern) {
            const float* kb = kern + ((bb * 9 + p) * Hk + row_out) * Wk;
            kv[0][0] = __ldg(kb + pixc[0][0]);
            kv[0][1] = __ldg(kb + pixc[0][1]);
            kv[1][0] = __ldg(kb + pixc[1][0]);
            kv[1][1] = __ldg(kb + pixc[1][1]);
        } else {
            kv[0][0] = kv[0][1] = kv[1][0] = kv[1][1] = 1.f;
        }

        const float* xrow = xb + row * Wk;

#pragma unroll
        for (int kh2 = 0; kh2 < 2; kh2++) {
            const int chb = kh2 * 32 + tq * 2;
            const uint2* bw =
                (const uint2*)(wt + p * 2048 + kh2 * 1024) + lane;

#pragma unroll
            for (int kc = 0; kc < 2; kc++) {
                // A fragments for this k16: regs [rr + kk*2]
                uint32_t fh[2][4], fl[2][4];   // [mh][reg]
#pragma unroll
                for (int mh = 0; mh < 2; mh++)
#pragma unroll
                    for (int kk = 0; kk < 2; kk++)
#pragma unroll
                        for (int rr = 0; rr < 2; rr++) {
                            const int ch  = chb + kc * 16 + kk * 8;
                            const int col = pixc[mh][rr] + dx;
                            const bool ok = (unsigned)col < 128u;
                            const float* s = xrow + (size_t)ch * NPIX + col;
                            float v0 = ok ? __ldg(s) : 0.f;
                            float v1 = ok ? __ldg(s + NPIX) : 0.f;
                            v0 *= kv[mh][rr];
                            v1 *= kv[mh][rr];
                            float2 vf; vf.x = v0; vf.y = v1;
                            __half2 hp = __float22half2_rn(vf);
                            float2 hb = __half22float2(hp);
                            float2 lf; lf.x = v0 - hb.x; lf.y = v1 - hb.y;
                            __half2 lp = __float22half2_rn(lf);
                            fh[mh][rr + kk * 2] = *(uint32_t*)&hp;
                            fl[mh][rr + kk * 2] = *(uint32_t*)&lp;
                        }

#pragma unroll
                for (int nc = 0; nc < 8; nc++) {
                    uint2 b = __ldg(bw + (kc * 8 + nc) * 32);
                    MMAF16(acc[0][nc], fh[0][0], fh[0][1], fh[0][2], fh[0][3],
                           b.x, b.y);
                    MMAF16(acc[0][nc], fl[0][0], fl[0][1], fl[0][2], fl[0][3],
                           b.x, b.y);
                    MMAF16(acc[1][nc], fh[1][0], fh[1][1], fh[1][2], fh[1][3],
                           b.x, b.y);
                    MMAF16(acc[1][nc], fl[1][0], fl[1][1], fl[1][2], fl[1][3],
                           b.x, b.y);
                }
            }
        }
    }

    // epilogue: acc[mh][nc] regs {0,1} -> pixel pixc[mh][0], {2,3} -> pixc[mh][1]
    const int rowoff0 = row_out * Wk;
#pragma unroll
    for (int mh = 0; mh < 2; mh++) {
#pragma unroll
        for (int nc = 0; nc < 8; nc++) {
            int o0 = nc * 8 + tq * 2;
            float bv0 = __ldg(bias + o0);
            float bv1 = __ldg(bias + o0 + 1);
            float v00 = acc[mh][nc][0] + bv0;
            float v01 = acc[mh][nc][1] + bv1;
            float v10 = acc[mh][nc][2] + bv0;
            float v11 = acc[mh][nc][3] + bv1;
            if (do_relu) {
                v00 = fmaxf(v00, 0.f); v01 = fmaxf(v01, 0.f);
                v10 = fmaxf(v10, 0.f); v11 = fmaxf(v11, 0.f);
            }
            int i00 = (bb * Ck + o0) * NPIX + rowoff0 + pixc[mh][0];
            if (resid) {
                v00 += resid[i00];
                v01 += resid[i00 + NPIX];
                v10 += resid[i00 + 8];
                v11 += resid[i00 + NPIX + 8];
            }
            out[i00] = v00;
            out[i00 + NPIX] = v01;
            out[i00 + 8] = v10;
            out[i00 + NPIX + 8] = v11;
        }
    }
}

// ---------------------------------------------------------------------------
extern "C" void kernel_launch(void* const* d_in, const int* in_sizes, int n_in,
                              void* d_out, int out_size) {
    const float* x      = (const float*)d_in[0];
    const float* edge   = (const float*)d_in[1];
    const float* w_pac1 = (const float*)d_in[2];
    const float* b_pac1 = (const float*)d_in[3];
    const float* w_pac2 = (const float*)d_in[4];
    const float* b_pac2 = (const float*)d_in[5];
    const float* w_e1   = (const float*)d_in[6];
    const float* b_e1   = (const float*)d_in[7];
    const float* w_e2   = (const float*)d_in[8];
    const float* b_e2   = (const float*)d_in[9];

    float* out_sr   = (float*)d_out;
    float* out_edge = out_sr + TENSOR;

    float *p_tmp_sr, *p_tmp_edge, *p_kern, *p_fields;
    uint32_t* p_wpk;
    cudaGetSymbolAddress((void**)&p_tmp_sr, g_tmp_sr);
    cudaGetSymbolAddress((void**)&p_tmp_edge, g_tmp_edge);
    cudaGetSymbolAddress((void**)&p_kern, g_kern);
    cudaGetSymbolAddress((void**)&p_fields, g_fields);
    cudaGetSymbolAddress((void**)&p_wpk, g_wpk);

    prep_weights<<<(4 * 9 * 2048 + 255) / 256, 256>>>(w_pac1, w_pac2, w_e1, w_e2);

    dim3 kgrid(Hk, Bk);
    dim3 cgrid(Hk / 2, Bk, 2);
    const int WS = 9 * 2048;

    // stage 1: kern(edge); z=0 pac(x), z=1 plain conv(edge); both relu
    field_kernel<<<kgrid, 128>>>(edge, p_fields);
    kern_assemble_kernel<<<kgrid, 128>>>(p_fields, p_kern);
    conv3x3_hmma_kernel<<<cgrid, 256>>>(
        x,    p_kern, p_wpk + 0 * WS, b_pac1, nullptr, p_tmp_sr,
        edge,         p_wpk + 2 * WS, b_e1,   nullptr, p_tmp_edge, 1);

    // stage 2: kern(tmp_edge); z=0 pac(tmp_sr)+x, z=1 conv(tmp_edge)+edge
    field_kernel<<<kgrid, 128>>>(p_tmp_edge, p_fields);
    kern_assemble_kernel<<<kgrid, 128>>>(p_fields, p_kern);
    conv3x3_hmma_kernel<<<cgrid, 256>>>(
        p_tmp_sr,   p_kern, p_wpk + 1 * WS, b_pac2, x,    out_sr,
        p_tmp_edge,         p_wpk + 3 * WS, b_e2,   edge, out_edge, 0);
}

// round 12
// speedup vs baseline: 4.3805x; 1.1907x over previous
#include <cuda_runtime.h>
#include <cuda_fp16.h>
#include <cstdint>
#include <math.h>

#define Bk 8
#define Ck 64
#define Hk 128
#define Wk 128
#define NPIX (Hk*Wk)                 // 16384
#define PLANE (Ck*NPIX)              // 1,048,576 per batch
#define TENSOR (Bk*PLANE)            // 8,388,608 elements
#define HPLANE (32*NPIX)             // half2 planes per batch

// ---------------------------------------------------------------------------
// Scratch (device globals; no allocation)
// ---------------------------------------------------------------------------
__device__ float   g_tmp_edge[TENSOR];          // fp32 tmp edge (guide for stage2)
__device__ float   g_kern[Bk * 9 * NPIX];
__device__ float   g_fields[Bk * 5 * NPIX];
__device__ __half2 g_xh[Bk * HPLANE];           // x        (channel-pair packed)
__device__ __half2 g_eh[Bk * HPLANE];           // edge
__device__ __half2 g_tsh[Bk * HPLANE];          // tmp_sr   (written by stage1)
__device__ __half2 g_teh[Bk * HPLANE];          // tmp_edge (written by stage1)
// packed fp16 weight fragments: [set 4][tap 9][kh 2][kc 2][nc 8][lane 32][reg 2]
__device__ uint32_t g_wpk[4 * 9 * 2048];

// ---------------------------------------------------------------------------
#define MMAF16(c, A0, A1, A2, A3, B0, B1)                                    \
    asm volatile(                                                            \
        "mma.sync.aligned.m16n8k16.row.col.f32.f16.f16.f32 "                 \
        "{%0,%1,%2,%3},{%4,%5,%6,%7},{%8,%9},{%0,%1,%2,%3};"                 \
        : "+f"((c)[0]), "+f"((c)[1]), "+f"((c)[2]), "+f"((c)[3])             \
        : "r"(A0), "r"(A1), "r"(A2), "r"(A3), "r"(B0), "r"(B1))

// ---------------------------------------------------------------------------
// Weight prep (single fp16 term)
// ---------------------------------------------------------------------------
__global__ void prep_weights(const float* __restrict__ w0,
                             const float* __restrict__ w1,
                             const float* __restrict__ w2,
                             const float* __restrict__ w3) {
    int idx = blockIdx.x * blockDim.x + threadIdx.x;
    if (idx >= 4 * 9 * 2048) return;
    int s    = idx / 18432;
    int rem  = idx % 18432;
    int p    = rem / 2048;
    int rem2 = rem % 2048;
    int kh   = (rem2 >> 10) & 1;
    int kc   = (rem2 >> 9) & 1;
    int nc   = (rem2 >> 6) & 7;
    int l    = (rem2 >> 1) & 31;
    int r    = rem2 & 1;

    int o = nc * 8 + (l >> 2);
    int k = kh * 32 + kc * 16 + (l & 3) * 2 + r * 8;

    const float* w = (s == 0) ? w0 : (s == 1) ? w1 : (s == 2) ? w2 : w3;
    float2 v;
    v.x = w[(o * 64 + k) * 9 + p];
    v.y = w[(o * 64 + k + 1) * 9 + p];
    __half2 h2 = __float22half2_rn(v);
    g_wpk[idx] = *(uint32_t*)&h2;
}

// ---------------------------------------------------------------------------
// Split fp32 NCHW -> channel-pair-packed half2 planes. blockIdx.y: 0=x, 1=edge
// ---------------------------------------------------------------------------
__global__ void __launch_bounds__(512)
split_kernel(const float* __restrict__ a, const float* __restrict__ b,
             __half2* __restrict__ ah, __half2* __restrict__ bh) {
    int idx = blockIdx.x * 512 + threadIdx.x;          // over Bk*32*NPIX
    const float* src = blockIdx.y ? b : a;
    __half2* dst = blockIdx.y ? bh : ah;
    int c2i = idx >> 14;                                // bb*32 + c2
    int q   = idx & (NPIX - 1);
    int base = (((c2i >> 5) << 6) + ((c2i & 31) << 1)) * NPIX + q;
    float2 v;
    v.x = src[base];
    v.y = src[base + NPIX];
    dst[idx] = __float22half2_rn(v);
}

// ---------------------------------------------------------------------------
// Pass A: per-pixel fields. sq; dot(0,1); dot(1,e), e=-1,0,1.
// ---------------------------------------------------------------------------
__global__ void __launch_bounds__(128)
field_kernel(const float* __restrict__ g, float* __restrict__ F) {
    const int h  = blockIdx.x;
    const int bb = blockIdx.y;
    const int w  = threadIdx.x;

    __shared__ float s[8][2][132];

    float sq = 0.f, d01 = 0.f, d1m = 0.f, d10 = 0.f, d1p = 0.f;

    const float* gb = g + bb * PLANE;
    const bool row1ok = (h + 1 < Hk);

    for (int c0 = 0; c0 < 64; c0 += 8) {
        if (c0) __syncthreads();
#pragma unroll
        for (int ch = 0; ch < 8; ch++) {
            const float* gc = gb + (c0 + ch) * NPIX;
            s[ch][0][w + 1] = gc[h * Wk + w];
            s[ch][1][w + 1] = row1ok ? gc[(h + 1) * Wk + w] : 0.f;
            if (w == 0) {
                s[ch][0][0] = 0.f; s[ch][1][0] = 0.f;
                s[ch][0][129] = 0.f; s[ch][1][129] = 0.f;
            }
        }
        __syncthreads();
#pragma unroll
        for (int ch = 0; ch < 8; ch++) {
            float c  = s[ch][0][w + 1];
            float r  = s[ch][0][w + 2];
            float bl = s[ch][1][w];
            float bc = s[ch][1][w + 1];
            float br = s[ch][1][w + 2];
            sq  += c * c;
            d01 += c * r;
            d1m += c * bl;
            d10 += c * bc;
            d1p += c * br;
        }
    }

    float* Fb = F + bb * 5 * NPIX + h * Wk + w;
    Fb[0 * NPIX] = sq;
    Fb[1 * NPIX] = d01;
    Fb[2 * NPIX] = d1m;
    Fb[3 * NPIX] = d10;
    Fb[4 * NPIX] = d1p;
}

// ---------------------------------------------------------------------------
// Pass B: kern[b][p][h][w] = exp(-0.5*(sq_nb + sq_c - 2*dot)).
// ---------------------------------------------------------------------------
__global__ void __launch_bounds__(128)
kern_assemble_kernel(const float* __restrict__ F, float* __restrict__ kout) {
    const int h  = blockIdx.x;
    const int bb = blockIdx.y;
    const int w  = threadIdx.x;

    const float* Fb = F + bb * 5 * NPIX;
    const float sqc = Fb[h * Wk + w];

    float* ko = kout + (bb * 9) * NPIX + h * Wk + w;

#pragma unroll
    for (int p = 0; p < 9; p++) {
        if (p == 4) { ko[4 * NPIX] = 1.0f; continue; }
        const int dy = p / 3 - 1, dx = p % 3 - 1;
        const int row = h + dy, col = w + dx;
        const bool inb = (row >= 0) && (row < Hk) && (col >= 0) && (col < Wk);
        float sqn = 0.f, dot = 0.f;
        if (inb) {
            sqn = Fb[row * Wk + col];
            if (dy == 0) {
                dot = (dx == 1) ? Fb[NPIX + h * Wk + w]
                                : Fb[NPIX + h * Wk + (w - 1)];
            } else if (dy == 1) {
                dot = Fb[(3 + dx) * NPIX + h * Wk + w];
            } else {
                dot = Fb[(3 - dx) * NPIX + (h - 1) * Wk + col];
            }
        }
        float d2 = sqn + sqc - 2.f * dot;
        ko[p * NPIX] = __expf(-0.5f * d2);
    }
}

// ---------------------------------------------------------------------------
// HMMA conv, single fp16 term, register-direct fragments, half2 inputs.
// Block = 2 image rows (M=256 pix, N=64 cout), 256 thr / 8 warps.
// Warp w: row h0+(w>>2), cols [(w&3)*32,+32). PAC kern folded via HMUL2.
// Outputs: half2-packed planes (outh) and/or fp32 NCHW (outf, with resid).
// ---------------------------------------------------------------------------
__global__ void __launch_bounds__(256, 2)
conv3x3_hmma_kernel(const __half2* __restrict__ xin0,
                    const float* __restrict__ kern0,   // null => plain
                    const uint32_t* __restrict__ wt0,
                    const float* __restrict__ bias0,
                    const float* __restrict__ resid0,
                    __half2* __restrict__ outh0,
                    float* __restrict__ outf0,
                    const __half2* __restrict__ xin1,
                    const uint32_t* __restrict__ wt1,
                    const float* __restrict__ bias1,
                    const float* __restrict__ resid1,
                    __half2* __restrict__ outh1,
                    float* __restrict__ outf1,
                    int do_relu) {
    const int h0 = blockIdx.x * 2;
    const int bb = blockIdx.y;
    const int z  = blockIdx.z;

    const __half2*  xin   = z ? xin1 : xin0;
    const float*    kern  = z ? nullptr : kern0;
    const uint32_t* wt    = z ? wt1 : wt0;
    const float*    bias  = z ? bias1 : bias0;
    const float*    resid = z ? resid1 : resid0;
    __half2*        outh  = z ? outh1 : outh0;
    float*          outf  = z ? outf1 : outf0;

    const int tid  = threadIdx.x;
    const int warp = tid >> 5;
    const int lane = tid & 31;
    const int gq   = lane >> 2;
    const int tq   = lane & 3;
    const int wr   = warp >> 2;
    const int c0   = (warp & 3) << 5;
    const int row_out = h0 + wr;

    int pixc[2][2];
    pixc[0][0] = c0 + gq;      pixc[0][1] = c0 + gq + 8;
    pixc[1][0] = c0 + 16 + gq; pixc[1][1] = c0 + 24 + gq;

    float acc[2][8][4];
#pragma unroll
    for (int mh = 0; mh < 2; mh++)
#pragma unroll
        for (int n = 0; n < 8; n++)
#pragma unroll
            for (int i = 0; i < 4; i++) acc[mh][n][i] = 0.f;

    const __half2* xb = xin + bb * HPLANE;

    for (int p = 0; p < 9; p++) {
        const int dy = p / 3 - 1, dx = p % 3 - 1;
        const int row = row_out + dy;
        if (row < 0 || row >= Hk) continue;

        // kern values at output pixels, as half2 broadcast
        __half2 kv2[2][2];
        if (kern) {
            const float* kb = kern + ((bb * 9 + p) * Hk + row_out) * Wk;
            kv2[0][0] = __float2half2_rn(__ldg(kb + pixc[0][0]));
            kv2[0][1] = __float2half2_rn(__ldg(kb + pixc[0][1]));
            kv2[1][0] = __float2half2_rn(__ldg(kb + pixc[1][0]));
            kv2[1][1] = __float2half2_rn(__ldg(kb + pixc[1][1]));
        }

        const __half2* xrow = xb + row * Wk;

#pragma unroll
        for (int kh2 = 0; kh2 < 2; kh2++) {
            const uint2* bw =
                (const uint2*)(wt + p * 2048 + kh2 * 1024) + lane;

#pragma unroll
            for (int kc = 0; kc < 2; kc++) {
                // A fragments: c2 planes kh2*16 + kc*8 + tq (+4)
                const int c2a = kh2 * 16 + kc * 8 + tq;
                uint32_t f[2][4];
#pragma unroll
                for (int mh = 0; mh < 2; mh++)
#pragma unroll
                    for (int kk = 0; kk < 2; kk++)
#pragma unroll
                        for (int rr = 0; rr < 2; rr++) {
                            const int col = pixc[mh][rr] + dx;
                            const bool ok = (unsigned)col < 128u;
                            __half2 v = ok
                                ? __ldg(xrow + (size_t)(c2a + kk * 4) * NPIX + col)
                                : __half2(__float2half2_rn(0.f));
                            if (kern) v = __hmul2(v, kv2[mh][rr]);
                            f[mh][rr + kk * 2] = *(uint32_t*)&v;
                        }

#pragma unroll
                for (int nc = 0; nc < 8; nc++) {
                    uint2 b = __ldg(bw + (kc * 8 + nc) * 32);
                    MMAF16(acc[0][nc], f[0][0], f[0][1], f[0][2], f[0][3],
                           b.x, b.y);
                    MMAF16(acc[1][nc], f[1][0], f[1][1], f[1][2], f[1][3],
                           b.x, b.y);
                }
            }
        }
    }

    // epilogue
    const int rowoff0 = row_out * Wk;
#pragma unroll
    for (int mh = 0; mh < 2; mh++) {
#pragma unroll
        for (int nc = 0; nc < 8; nc++) {
            int o0 = nc * 8 + tq * 2;
            float bv0 = __ldg(bias + o0);
            float bv1 = __ldg(bias + o0 + 1);
            float v00 = acc[mh][nc][0] + bv0;
            float v01 = acc[mh][nc][1] + bv1;
            float v10 = acc[mh][nc][2] + bv0;
            float v11 = acc[mh][nc][3] + bv1;
            if (do_relu) {
                v00 = fmaxf(v00, 0.f); v01 = fmaxf(v01, 0.f);
                v10 = fmaxf(v10, 0.f); v11 = fmaxf(v11, 0.f);
            }
            if (outh) {
                // half2-packed planes: plane (o0>>1), low = even cout
                size_t ha = (size_t)(bb * 32 + (o0 >> 1)) * NPIX + rowoff0;
                float2 p0; p0.x = v00; p0.y = v01;
                float2 p1; p1.x = v10; p1.y = v11;
                outh[ha + pixc[mh][0]] = __float22half2_rn(p0);
                outh[ha + pixc[mh][1]] = __float22half2_rn(p1);
            }
            if (outf) {
                int i00 = (bb * Ck + o0) * NPIX + rowoff0 + pixc[mh][0];
                if (resid) {
                    v00 += resid[i00];
                    v01 += resid[i00 + NPIX];
                    v10 += resid[i00 + 8];
                    v11 += resid[i00 + NPIX + 8];
                }
                outf[i00] = v00;
                outf[i00 + NPIX] = v01;
                outf[i00 + 8] = v10;
                outf[i00 + NPIX + 8] = v11;
            }
        }
    }
}

// ---------------------------------------------------------------------------
extern "C" void kernel_launch(void* const* d_in, const int* in_sizes, int n_in,
                              void* d_out, int out_size) {
    const float* x      = (const float*)d_in[0];
    const float* edge   = (const float*)d_in[1];
    const float* w_pac1 = (const float*)d_in[2];
    const float* b_pac1 = (const float*)d_in[3];
    const float* w_pac2 = (const float*)d_in[4];
    const float* b_pac2 = (const float*)d_in[5];
    const float* w_e1   = (const float*)d_in[6];
    const float* b_e1   = (const float*)d_in[7];
    const float* w_e2   = (const float*)d_in[8];
    const float* b_e2   = (const float*)d_in[9];

    float* out_sr   = (float*)d_out;
    float* out_edge = out_sr + TENSOR;

    float *p_tmp_edge, *p_kern, *p_fields;
    __half2 *p_xh, *p_eh, *p_tsh, *p_teh;
    uint32_t* p_wpk;
    cudaGetSymbolAddress((void**)&p_tmp_edge, g_tmp_edge);
    cudaGetSymbolAddress((void**)&p_kern, g_kern);
    cudaGetSymbolAddress((void**)&p_fields, g_fields);
    cudaGetSymbolAddress((void**)&p_xh, g_xh);
    cudaGetSymbolAddress((void**)&p_eh, g_eh);
    cudaGetSymbolAddress((void**)&p_tsh, g_tsh);
    cudaGetSymbolAddress((void**)&p_teh, g_teh);
    cudaGetSymbolAddress((void**)&p_wpk, g_wpk);

    prep_weights<<<(4 * 9 * 2048 + 255) / 256, 256>>>(w_pac1, w_pac2, w_e1, w_e2);

    // split x, edge into half2-packed planes
    {
        dim3 sgrid((Bk * HPLANE + 511) / 512, 2);
        split_kernel<<<sgrid, 512>>>(x, edge, p_xh, p_eh);
    }

    dim3 kgrid(Hk, Bk);
    dim3 cgrid(Hk / 2, Bk, 2);
    const int WS = 9 * 2048;

    // stage 1: kern(edge); z=0 pac(x) -> tsh (half), z=1 conv(edge) -> teh + fp32
    field_kernel<<<kgrid, 128>>>(edge, p_fields);
    kern_assemble_kernel<<<kgrid, 128>>>(p_fields, p_kern);
    conv3x3_hmma_kernel<<<cgrid, 256>>>(
        p_xh, p_kern, p_wpk + 0 * WS, b_pac1, nullptr, p_tsh, nullptr,
        p_eh,         p_wpk + 2 * WS, b_e1,   nullptr, p_teh, p_tmp_edge, 1);

    // stage 2: kern(tmp_edge); z=0 pac(tsh)+x -> out_sr, z=1 conv(teh)+edge -> out_edge
    field_kernel<<<kgrid, 128>>>(p_tmp_edge, p_fields);
    kern_assemble_kernel<<<kgrid, 128>>>(p_fields, p_kern);
    conv3x3_hmma_kernel<<<cgrid, 256>>>(
        p_tsh, p_kern, p_wpk + 1 * WS, b_pac2, x,    nullptr, out_sr,
        p_teh,         p_wpk + 3 * WS, b_e2,   edge, nullptr, out_edge, 0);
}